// round 7
// baseline (speedup 1.0000x reference)
#include <cuda_runtime.h>

#define N_NODES 100000
#define E_MAX   3200000
#define F_XD    64
#define F_UD    128
#define F_OUTD  128
#define B_GLOB  512
#define SCAN_B  1024

typedef unsigned long long ull;

__device__ float g_agg[N_NODES * F_XD];
__device__ float g_U[B_GLOB * 256];
__device__ int   g_is64;
__device__ int   g_deg[N_NODES];
__device__ int   g_rowptr[N_NODES];
__device__ int   g_cursor[N_NODES];
__device__ int   g_bsum[512];
__device__ int   g_boff[512];
__device__ uint2 g_edges[E_MAX];

__device__ __forceinline__ ull pack2(float a, float b) {
    ull r; asm("mov.b64 %0, {%1, %2};" : "=l"(r) : "f"(a), "f"(b)); return r;
}
__device__ __forceinline__ void ffma2(ull& d, ull a, ull b) {
    asm("fma.rn.f32x2 %0, %1, %2, %0;" : "+l"(d) : "l"(a), "l"(b));
}
__device__ __forceinline__ ull add2(ull a, ull b) {
    ull r; asm("add.rn.f32x2 %0, %1, %2;" : "=l"(r) : "l"(a), "l"(b)); return r;
}

// ---------------------------------------------------------------------------
// zero degree counters + index-dtype probe
// ---------------------------------------------------------------------------
__global__ void zero_probe_kernel(const void* __restrict__ ei, int E, int N) {
    int i = blockIdx.x * blockDim.x + threadIdx.x;
    if (i < N) g_deg[i] = 0;
    if (i == 0) {
        const long long* p = (const long long*)ei;
        long long stride = (2LL * E) / 64;
        int ok = 1;
        for (int j = 0; j < 64; j++) {
            long long v = p[(long long)j * stride];
            if (v < 0 || v >= N) { ok = 0; break; }
        }
        g_is64 = ok;
    }
}

// ---------------------------------------------------------------------------
// in-degree histogram (int4-vectorized on int32 path)
// ---------------------------------------------------------------------------
__global__ void hist_kernel(const void* __restrict__ ei, int E) {
    const int is64 = g_is64;
    int t = blockIdx.x * blockDim.x + threadIdx.x;
    if (!is64) {
        int n4 = E >> 2;
        if (t < n4) {
            int4 d4 = reinterpret_cast<const int4*>((const int*)ei + E)[t];
            atomicAdd(&g_deg[d4.x], 1);
            atomicAdd(&g_deg[d4.y], 1);
            atomicAdd(&g_deg[d4.z], 1);
            atomicAdd(&g_deg[d4.w], 1);
        }
        int tail = E & 3;
        if (t < tail)
            atomicAdd(&g_deg[((const int*)ei)[E + (E - tail) + t]], 1);
    } else {
        for (int e = t; e < E; e += gridDim.x * blockDim.x)
            atomicAdd(&g_deg[(int)((const long long*)ei)[E + e]], 1);
    }
}

// ---------------------------------------------------------------------------
// Exclusive scan (3 phases; phase 2 now a parallel block scan)
// ---------------------------------------------------------------------------
__global__ void scan1_kernel(int N) {
    __shared__ int ss[256];
    int b = blockIdx.x, t = threadIdx.x;
    int base = b * SCAN_B + t * 4;
    int s = 0;
#pragma unroll
    for (int j = 0; j < 4; j++) { int idx = base + j; if (idx < N) s += g_deg[idx]; }
    ss[t] = s;
    __syncthreads();
    for (int off = 128; off > 0; off >>= 1) {
        if (t < off) ss[t] += ss[t + off];
        __syncthreads();
    }
    if (t == 0) g_bsum[b] = ss[0];
}

__global__ void scan2_kernel(int nblk) {
    __shared__ int ss[512];
    int t = threadIdx.x;
    int v = (t < nblk) ? g_bsum[t] : 0;
    ss[t] = v;
    __syncthreads();
    for (int off = 1; off < 512; off <<= 1) {
        int add = (t >= off) ? ss[t - off] : 0;
        __syncthreads();
        ss[t] += add;
        __syncthreads();
    }
    if (t < nblk) g_boff[t] = ss[t] - v;
}

__global__ void scan3_kernel(int N) {
    __shared__ int ss[256];
    int b = blockIdx.x, t = threadIdx.x;
    int base = b * SCAN_B + t * 4;
    int v[4]; int tsum = 0;
#pragma unroll
    for (int j = 0; j < 4; j++) {
        int idx = base + j;
        v[j] = (idx < N) ? g_deg[idx] : 0;
        tsum += v[j];
    }
    ss[t] = tsum;
    __syncthreads();
    for (int off = 1; off < 256; off <<= 1) {
        int add = (t >= off) ? ss[t - off] : 0;
        __syncthreads();
        ss[t] += add;
        __syncthreads();
    }
    int run = g_boff[b] + ss[t] - tsum;
#pragma unroll
    for (int j = 0; j < 4; j++) {
        int idx = base + j;
        if (idx < N) { g_rowptr[idx] = run; g_cursor[idx] = run; }
        run += v[j];
    }
}

// ---------------------------------------------------------------------------
// bucket edges by dest (vectorized on int32 path)
// ---------------------------------------------------------------------------
__global__ void fill_kernel(const void*  __restrict__ ei,
                            const float* __restrict__ attr, int E) {
    const int is64 = g_is64;
    int t = blockIdx.x * blockDim.x + threadIdx.x;
    if (!is64) {
        int n4 = E >> 2;
        if (t < n4) {
            int4   s4 = ((const int4*)((const int*)ei))[t];
            int4   d4 = ((const int4*)((const int*)ei + E))[t];
            float4 a4 = ((const float4*)attr)[t];
            int p0 = atomicAdd(&g_cursor[d4.x], 1);
            g_edges[p0] = make_uint2((unsigned)s4.x, __float_as_uint(a4.x));
            int p1 = atomicAdd(&g_cursor[d4.y], 1);
            g_edges[p1] = make_uint2((unsigned)s4.y, __float_as_uint(a4.y));
            int p2 = atomicAdd(&g_cursor[d4.z], 1);
            g_edges[p2] = make_uint2((unsigned)s4.z, __float_as_uint(a4.z));
            int p3 = atomicAdd(&g_cursor[d4.w], 1);
            g_edges[p3] = make_uint2((unsigned)s4.w, __float_as_uint(a4.w));
        }
        int tail = E & 3;
        if (t < tail) {
            int e = (E - tail) + t;
            int s = ((const int*)ei)[e];
            int d = ((const int*)ei)[E + e];
            int pos = atomicAdd(&g_cursor[d], 1);
            g_edges[pos] = make_uint2((unsigned)s, __float_as_uint(attr[e]));
        }
    } else {
        for (int e = t; e < E; e += gridDim.x * blockDim.x) {
            int s = (int)((const long long*)ei)[e];
            int d = (int)((const long long*)ei)[E + e];
            int pos = atomicAdd(&g_cursor[d], 1);
            g_edges[pos] = make_uint2((unsigned)s, __float_as_uint(attr[e]));
        }
    }
}

// ---------------------------------------------------------------------------
// Aggregate: one warp per dest, lane owns 2 cols; uint4 paired edge loads.
// ---------------------------------------------------------------------------
__global__ void __launch_bounds__(256)
agg_kernel(const float* __restrict__ x, int N) {
    int t    = blockIdx.x * blockDim.x + threadIdx.x;
    int lane = t & 31;
    int d    = t >> 5;
    if (d >= N) return;

    int start = g_rowptr[d];
    int deg   = g_deg[d];
    const float* xb = x + lane * 2;

    ull a0 = 0, a1 = 0, a2 = 0, a3 = 0;
    int i = 0;
    if (deg > 0 && (start & 1)) {
        uint2 e = g_edges[start];
        ull v = *reinterpret_cast<const ull*>(xb + (size_t)e.x * F_XD);
        float wv = __uint_as_float(e.y);
        ffma2(a0, v, pack2(wv, wv));
        i = 1;
    }
    for (; i + 4 <= deg; i += 4) {
        const uint4* ep = (const uint4*)(g_edges + start + i);
        uint4 p0 = ep[0];
        uint4 p1 = ep[1];
        ull v0 = *reinterpret_cast<const ull*>(xb + (size_t)p0.x * F_XD);
        ull v1 = *reinterpret_cast<const ull*>(xb + (size_t)p0.z * F_XD);
        ull v2 = *reinterpret_cast<const ull*>(xb + (size_t)p1.x * F_XD);
        ull v3 = *reinterpret_cast<const ull*>(xb + (size_t)p1.z * F_XD);
        float w0 = __uint_as_float(p0.y), w1 = __uint_as_float(p0.w);
        float w2 = __uint_as_float(p1.y), w3 = __uint_as_float(p1.w);
        ffma2(a0, v0, pack2(w0, w0));
        ffma2(a1, v1, pack2(w1, w1));
        ffma2(a2, v2, pack2(w2, w2));
        ffma2(a3, v3, pack2(w3, w3));
    }
    for (; i < deg; i++) {
        uint2 e = g_edges[start + i];
        ull v = *reinterpret_cast<const ull*>(xb + (size_t)e.x * F_XD);
        float wv = __uint_as_float(e.y);
        ffma2(a0, v, pack2(wv, wv));
    }
    ull s = add2(add2(a0, a1), add2(a2, a3));
    *reinterpret_cast<ull*>(g_agg + (size_t)d * F_XD + lane * 2) = s;
}

// ---------------------------------------------------------------------------
// u-projection: 4 batch rows per block
// ---------------------------------------------------------------------------
__global__ void u_proj_kernel(const float* __restrict__ u,
                              const float* __restrict__ WK, const float* __restrict__ bK,
                              const float* __restrict__ WQ, const float* __restrict__ bQ) {
    __shared__ float su[4][F_UD];
    int b0 = blockIdx.x * 4;
    int j  = threadIdx.x;
    for (int i = j; i < 4 * F_UD; i += 256)
        su[i >> 7][i & 127] = u[(b0 + (i >> 7)) * F_UD + (i & 127)];
    __syncthreads();

    const float* W   = (j < F_OUTD) ? WK : WQ;
    int          col = j & (F_OUTD - 1);
    float bias = (j < F_OUTD) ? bK[col] : bQ[col];
    float a0 = bias, a1 = bias, a2 = bias, a3 = bias;
#pragma unroll 4
    for (int k = 0; k < F_UD; k++) {
        float wv = W[(F_XD + k) * F_OUTD + col];
        a0 = fmaf(su[0][k], wv, a0);
        a1 = fmaf(su[1][k], wv, a1);
        a2 = fmaf(su[2][k], wv, a2);
        a3 = fmaf(su[3][k], wv, a3);
    }
    g_U[(b0 + 0) * 256 + j] = a0;
    g_U[(b0 + 1) * 256 + j] = a1;
    g_U[(b0 + 2) * 256 + j] = a2;
    g_U[(b0 + 3) * 256 + j] = a3;
}

// ---------------------------------------------------------------------------
// Fused projection v2: 128-node x 256-col tile, 512 threads.
// Thread tile: 8 nodes x 8 cols. Warp layout: lane = col-group, warp = node-
// group => sA reads are warp-broadcast (free), sW reads conflict-free.
// ---------------------------------------------------------------------------
#define ASP 130   // sA row stride (even for 8B alignment)

__global__ void __launch_bounds__(512, 1)
proj_kernel(const void* __restrict__ batch,
            const float* __restrict__ WK,
            const float* __restrict__ WQ,
            float* __restrict__ out, int N) {
    extern __shared__ float sh[];
    float* sW = sh;                 // [64][256]
    float* sA = sh + 64 * 256;      // [64][ASP], transposed agg tile (128 nodes)
    __shared__ int sB[128];

    int tid   = threadIdx.x;
    int node0 = blockIdx.x * 128;

    // Stage W rows 0..63 of [W_K | W_Q]
    for (int i = tid; i < 64 * 64; i += 512) {
        int k = i >> 6;
        int j = (i & 63) * 4;
        float4 v;
        if (j < 128) v = *reinterpret_cast<const float4*>(WK + k * 128 + j);
        else         v = *reinterpret_cast<const float4*>(WQ + k * 128 + (j - 128));
        *reinterpret_cast<float4*>(sW + k * 256 + j) = v;
    }
    // Stage agg tile transposed: sA[k][n], 128 nodes
    for (int i = tid; i < 128 * 64; i += 512) {
        int n = i >> 6;
        int k = i & 63;
        int gn = node0 + n;
        sA[k * ASP + n] = (gn < N) ? g_agg[(size_t)gn * F_XD + k] : 0.f;
    }
    if (tid < 128) {
        int gn = node0 + tid;
        int b = 0;
        if (gn < N) {
            if (g_is64) b = (int)((const long long*)batch)[gn];
            else        b = ((const int*)batch)[gn];
        }
        sB[tid] = b;
    }
    __syncthreads();

    int lane = tid & 31;       // 32 col groups x 8 cols = 256 cols
    int wrp  = tid >> 5;       // 16 node groups x 8 nodes = 128 nodes
    int c0 = lane * 8;
    int n0 = wrp * 8;

    ull acc[4][8];             // [node-pair][col]
#pragma unroll
    for (int p = 0; p < 4; p++)
#pragma unroll
        for (int c = 0; c < 8; c++) acc[p][c] = 0ull;

#pragma unroll 4
    for (int k = 0; k < 64; k++) {
        // broadcast loads: all lanes in the warp read the same 8 node values
        const float* ar = sA + k * ASP + n0;
        ull a0 = *reinterpret_cast<const ull*>(ar + 0);
        ull a1 = *reinterpret_cast<const ull*>(ar + 2);
        ull a2 = *reinterpret_cast<const ull*>(ar + 4);
        ull a3 = *reinterpret_cast<const ull*>(ar + 6);
        // per-lane 8 consecutive weights
        float4 wv0 = *reinterpret_cast<const float4*>(sW + k * 256 + c0);
        float4 wv1 = *reinterpret_cast<const float4*>(sW + k * 256 + c0 + 4);
        ull w2[8] = { pack2(wv0.x, wv0.x), pack2(wv0.y, wv0.y),
                      pack2(wv0.z, wv0.z), pack2(wv0.w, wv0.w),
                      pack2(wv1.x, wv1.x), pack2(wv1.y, wv1.y),
                      pack2(wv1.z, wv1.z), pack2(wv1.w, wv1.w) };
#pragma unroll
        for (int c = 0; c < 8; c++) {
            ffma2(acc[0][c], a0, w2[c]);
            ffma2(acc[1][c], a1, w2[c]);
            ffma2(acc[2][c], a2, w2[c]);
            ffma2(acc[3][c], a3, w2[c]);
        }
    }

    float* outK = out;
    float* outQ = out + (size_t)N * 128;
    bool  isK  = (c0 < 128);
    int   cc   = isK ? c0 : (c0 - 128);
    float* ob  = isK ? outK : outQ;

#pragma unroll
    for (int p = 0; p < 4; p++) {
        int nA = n0 + 2 * p, nB = nA + 1;
        int gA = node0 + nA, gB = node0 + nB;
        const float* uAr = g_U + sB[nA] * 256 + c0;
        const float* uBr = g_U + sB[nB] * 256 + c0;
        float4 uA0 = *reinterpret_cast<const float4*>(uAr);
        float4 uA1 = *reinterpret_cast<const float4*>(uAr + 4);
        float4 uB0 = *reinterpret_cast<const float4*>(uBr);
        float4 uB1 = *reinterpret_cast<const float4*>(uBr + 4);

        float2 f[8];
#pragma unroll
        for (int c = 0; c < 8; c++) f[c] = *reinterpret_cast<float2*>(&acc[p][c]);

        float4 a0 = make_float4(f[0].x + uA0.x, f[1].x + uA0.y,
                                f[2].x + uA0.z, f[3].x + uA0.w);
        float4 a1 = make_float4(f[4].x + uA1.x, f[5].x + uA1.y,
                                f[6].x + uA1.z, f[7].x + uA1.w);
        float4 b0 = make_float4(f[0].y + uB0.x, f[1].y + uB0.y,
                                f[2].y + uB0.z, f[3].y + uB0.w);
        float4 b1 = make_float4(f[4].y + uB1.x, f[5].y + uB1.y,
                                f[6].y + uB1.z, f[7].y + uB1.w);

        if (gA < N) {
            *reinterpret_cast<float4*>(ob + (size_t)gA * 128 + cc)     = a0;
            *reinterpret_cast<float4*>(ob + (size_t)gA * 128 + cc + 4) = a1;
        }
        if (gB < N) {
            *reinterpret_cast<float4*>(ob + (size_t)gB * 128 + cc)     = b0;
            *reinterpret_cast<float4*>(ob + (size_t)gB * 128 + cc + 4) = b1;
        }
    }
}

// ---------------------------------------------------------------------------
extern "C" void kernel_launch(void* const* d_in, const int* in_sizes, int n_in,
                              void* d_out, int out_size) {
    const float* x     = (const float*)d_in[0];
    const void*  ei    = d_in[1];
    const float* attr  = (const float*)d_in[2];
    const float* u     = (const float*)d_in[3];
    const void*  batch = d_in[4];
    const float* WK    = (const float*)d_in[5];
    const float* bK    = (const float*)d_in[6];
    const float* WQ    = (const float*)d_in[7];
    const float* bQ    = (const float*)d_in[8];
    float*       out   = (float*)d_out;

    int E = in_sizes[2];
    int N = in_sizes[4];
    int nblk = (N + SCAN_B - 1) / SCAN_B;

    zero_probe_kernel<<<(N + 255) / 256, 256>>>(ei, E, N);
    hist_kernel<<<((E >> 2) + 255) / 256, 256>>>(ei, E);
    scan1_kernel<<<nblk, 256>>>(N);
    scan2_kernel<<<1, 512>>>(nblk);
    scan3_kernel<<<nblk, 256>>>(N);
    fill_kernel<<<((E >> 2) + 255) / 256, 256>>>(ei, attr, E);
    agg_kernel<<<(N * 32 + 255) / 256, 256>>>(x, N);

    u_proj_kernel<<<B_GLOB / 4, 256>>>(u, WK, bK, WQ, bQ);

    int smem = (64 * 256 + 64 * ASP) * (int)sizeof(float);
    cudaFuncSetAttribute(proj_kernel, cudaFuncAttributeMaxDynamicSharedMemorySize, smem);
    proj_kernel<<<(N + 127) / 128, 512, smem>>>(batch, WK, WQ, out, N);
}

// round 8
// speedup vs baseline: 1.1598x; 1.1598x over previous
#include <cuda_runtime.h>

#define N_NODES 100000
#define E_MAX   3200000
#define F_XD    64
#define F_UD    128
#define F_OUTD  128
#define B_GLOB  512
#define SCAN_B  1024

typedef unsigned long long ull;

__device__ float g_agg[N_NODES * F_XD];
__device__ float g_U[B_GLOB * 256];
__device__ int   g_is64;
__device__ int   g_deg[N_NODES];
__device__ int   g_rowptr[N_NODES];
__device__ int   g_cursor[N_NODES];
__device__ int   g_bsum[512];
__device__ int   g_boff[512];
__device__ uint2 g_edges[E_MAX];

__device__ __forceinline__ ull pack2(float a, float b) {
    ull r; asm("mov.b64 %0, {%1, %2};" : "=l"(r) : "f"(a), "f"(b)); return r;
}
__device__ __forceinline__ void ffma2(ull& d, ull a, ull b) {
    asm("fma.rn.f32x2 %0, %1, %2, %0;" : "+l"(d) : "l"(a), "l"(b));
}
__device__ __forceinline__ ull add2(ull a, ull b) {
    ull r; asm("add.rn.f32x2 %0, %1, %2;" : "=l"(r) : "l"(a), "l"(b)); return r;
}

// ---------------------------------------------------------------------------
// zero degree counters + index-dtype probe
// ---------------------------------------------------------------------------
__global__ void zero_probe_kernel(const void* __restrict__ ei, int E, int N) {
    int i = blockIdx.x * blockDim.x + threadIdx.x;
    if (i < N) g_deg[i] = 0;
    if (i == 0) {
        const long long* p = (const long long*)ei;
        long long stride = (2LL * E) / 64;
        int ok = 1;
        for (int j = 0; j < 64; j++) {
            long long v = p[(long long)j * stride];
            if (v < 0 || v >= N) { ok = 0; break; }
        }
        g_is64 = ok;
    }
}

// ---------------------------------------------------------------------------
// in-degree histogram (int4-vectorized on int32 path)
// ---------------------------------------------------------------------------
__global__ void hist_kernel(const void* __restrict__ ei, int E) {
    const int is64 = g_is64;
    int t = blockIdx.x * blockDim.x + threadIdx.x;
    if (!is64) {
        int n4 = E >> 2;
        if (t < n4) {
            int4 d4 = reinterpret_cast<const int4*>((const int*)ei + E)[t];
            atomicAdd(&g_deg[d4.x], 1);
            atomicAdd(&g_deg[d4.y], 1);
            atomicAdd(&g_deg[d4.z], 1);
            atomicAdd(&g_deg[d4.w], 1);
        }
        int tail = E & 3;
        if (t < tail)
            atomicAdd(&g_deg[((const int*)ei)[E + (E - tail) + t]], 1);
    } else {
        for (int e = t; e < E; e += gridDim.x * blockDim.x)
            atomicAdd(&g_deg[(int)((const long long*)ei)[E + e]], 1);
    }
}

// ---------------------------------------------------------------------------
// Exclusive scan (3 phases)
// ---------------------------------------------------------------------------
__global__ void scan1_kernel(int N) {
    __shared__ int ss[256];
    int b = blockIdx.x, t = threadIdx.x;
    int base = b * SCAN_B + t * 4;
    int s = 0;
#pragma unroll
    for (int j = 0; j < 4; j++) { int idx = base + j; if (idx < N) s += g_deg[idx]; }
    ss[t] = s;
    __syncthreads();
    for (int off = 128; off > 0; off >>= 1) {
        if (t < off) ss[t] += ss[t + off];
        __syncthreads();
    }
    if (t == 0) g_bsum[b] = ss[0];
}

__global__ void scan2_kernel(int nblk) {
    __shared__ int ss[512];
    int t = threadIdx.x;
    int v = (t < nblk) ? g_bsum[t] : 0;
    ss[t] = v;
    __syncthreads();
    for (int off = 1; off < 512; off <<= 1) {
        int add = (t >= off) ? ss[t - off] : 0;
        __syncthreads();
        ss[t] += add;
        __syncthreads();
    }
    if (t < nblk) g_boff[t] = ss[t] - v;
}

__global__ void scan3_kernel(int N) {
    __shared__ int ss[256];
    int b = blockIdx.x, t = threadIdx.x;
    int base = b * SCAN_B + t * 4;
    int v[4]; int tsum = 0;
#pragma unroll
    for (int j = 0; j < 4; j++) {
        int idx = base + j;
        v[j] = (idx < N) ? g_deg[idx] : 0;
        tsum += v[j];
    }
    ss[t] = tsum;
    __syncthreads();
    for (int off = 1; off < 256; off <<= 1) {
        int add = (t >= off) ? ss[t - off] : 0;
        __syncthreads();
        ss[t] += add;
        __syncthreads();
    }
    int run = g_boff[b] + ss[t] - tsum;
#pragma unroll
    for (int j = 0; j < 4; j++) {
        int idx = base + j;
        if (idx < N) { g_rowptr[idx] = run; g_cursor[idx] = run; }
        run += v[j];
    }
}

// ---------------------------------------------------------------------------
// bucket edges by dest (vectorized on int32 path)
// ---------------------------------------------------------------------------
__global__ void fill_kernel(const void*  __restrict__ ei,
                            const float* __restrict__ attr, int E) {
    const int is64 = g_is64;
    int t = blockIdx.x * blockDim.x + threadIdx.x;
    if (!is64) {
        int n4 = E >> 2;
        if (t < n4) {
            int4   s4 = ((const int4*)((const int*)ei))[t];
            int4   d4 = ((const int4*)((const int*)ei + E))[t];
            float4 a4 = ((const float4*)attr)[t];
            int p0 = atomicAdd(&g_cursor[d4.x], 1);
            g_edges[p0] = make_uint2((unsigned)s4.x, __float_as_uint(a4.x));
            int p1 = atomicAdd(&g_cursor[d4.y], 1);
            g_edges[p1] = make_uint2((unsigned)s4.y, __float_as_uint(a4.y));
            int p2 = atomicAdd(&g_cursor[d4.z], 1);
            g_edges[p2] = make_uint2((unsigned)s4.z, __float_as_uint(a4.z));
            int p3 = atomicAdd(&g_cursor[d4.w], 1);
            g_edges[p3] = make_uint2((unsigned)s4.w, __float_as_uint(a4.w));
        }
        int tail = E & 3;
        if (t < tail) {
            int e = (E - tail) + t;
            int s = ((const int*)ei)[e];
            int d = ((const int*)ei)[E + e];
            int pos = atomicAdd(&g_cursor[d], 1);
            g_edges[pos] = make_uint2((unsigned)s, __float_as_uint(attr[e]));
        }
    } else {
        for (int e = t; e < E; e += gridDim.x * blockDim.x) {
            int s = (int)((const long long*)ei)[e];
            int d = (int)((const long long*)ei)[E + e];
            int pos = atomicAdd(&g_cursor[d], 1);
            g_edges[pos] = make_uint2((unsigned)s, __float_as_uint(attr[e]));
        }
    }
}

// ---------------------------------------------------------------------------
// Aggregate: one warp per dest, lane owns 2 cols; uint4 paired edge loads.
// ---------------------------------------------------------------------------
__global__ void __launch_bounds__(256)
agg_kernel(const float* __restrict__ x, int N) {
    int t    = blockIdx.x * blockDim.x + threadIdx.x;
    int lane = t & 31;
    int d    = t >> 5;
    if (d >= N) return;

    int start = g_rowptr[d];
    int deg   = g_deg[d];
    const float* xb = x + lane * 2;

    ull a0 = 0, a1 = 0, a2 = 0, a3 = 0;
    int i = 0;
    if (deg > 0 && (start & 1)) {
        uint2 e = g_edges[start];
        ull v = *reinterpret_cast<const ull*>(xb + (size_t)e.x * F_XD);
        float wv = __uint_as_float(e.y);
        ffma2(a0, v, pack2(wv, wv));
        i = 1;
    }
    for (; i + 4 <= deg; i += 4) {
        const uint4* ep = (const uint4*)(g_edges + start + i);
        uint4 p0 = ep[0];
        uint4 p1 = ep[1];
        ull v0 = *reinterpret_cast<const ull*>(xb + (size_t)p0.x * F_XD);
        ull v1 = *reinterpret_cast<const ull*>(xb + (size_t)p0.z * F_XD);
        ull v2 = *reinterpret_cast<const ull*>(xb + (size_t)p1.x * F_XD);
        ull v3 = *reinterpret_cast<const ull*>(xb + (size_t)p1.z * F_XD);
        float w0 = __uint_as_float(p0.y), w1 = __uint_as_float(p0.w);
        float w2 = __uint_as_float(p1.y), w3 = __uint_as_float(p1.w);
        ffma2(a0, v0, pack2(w0, w0));
        ffma2(a1, v1, pack2(w1, w1));
        ffma2(a2, v2, pack2(w2, w2));
        ffma2(a3, v3, pack2(w3, w3));
    }
    for (; i < deg; i++) {
        uint2 e = g_edges[start + i];
        ull v = *reinterpret_cast<const ull*>(xb + (size_t)e.x * F_XD);
        float wv = __uint_as_float(e.y);
        ffma2(a0, v, pack2(wv, wv));
    }
    ull s = add2(add2(a0, a1), add2(a2, a3));
    *reinterpret_cast<ull*>(g_agg + (size_t)d * F_XD + lane * 2) = s;
}

// ---------------------------------------------------------------------------
// u-projection: 4 batch rows per block
// ---------------------------------------------------------------------------
__global__ void u_proj_kernel(const float* __restrict__ u,
                              const float* __restrict__ WK, const float* __restrict__ bK,
                              const float* __restrict__ WQ, const float* __restrict__ bQ) {
    __shared__ float su[4][F_UD];
    int b0 = blockIdx.x * 4;
    int j  = threadIdx.x;
    for (int i = j; i < 4 * F_UD; i += 256)
        su[i >> 7][i & 127] = u[(b0 + (i >> 7)) * F_UD + (i & 127)];
    __syncthreads();

    const float* W   = (j < F_OUTD) ? WK : WQ;
    int          col = j & (F_OUTD - 1);
    float bias = (j < F_OUTD) ? bK[col] : bQ[col];
    float a0 = bias, a1 = bias, a2 = bias, a3 = bias;
#pragma unroll 4
    for (int k = 0; k < F_UD; k++) {
        float wv = W[(F_XD + k) * F_OUTD + col];
        a0 = fmaf(su[0][k], wv, a0);
        a1 = fmaf(su[1][k], wv, a1);
        a2 = fmaf(su[2][k], wv, a2);
        a3 = fmaf(su[3][k], wv, a3);
    }
    g_U[(b0 + 0) * 256 + j] = a0;
    g_U[(b0 + 1) * 256 + j] = a1;
    g_U[(b0 + 2) * 256 + j] = a2;
    g_U[(b0 + 3) * 256 + j] = a3;
}

// ---------------------------------------------------------------------------
// Fused projection (R4 shape): 64-node tile, 512 threads, 8n x 4c per thread.
// AS=68 (mult of 4) -> A broadcast loads are two LDS.128 instead of 4 LDS.64.
// sA staged with float4 gmem reads.
// ---------------------------------------------------------------------------
#define AS2 68

__global__ void __launch_bounds__(512)
proj_kernel(const void* __restrict__ batch,
            const float* __restrict__ WK,
            const float* __restrict__ WQ,
            float* __restrict__ out, int N) {
    extern __shared__ float sh[];
    float* sW = sh;                 // [64][256]
    float* sA = sh + 64 * 256;      // [64][AS2]
    __shared__ int sB[64];

    int tid   = threadIdx.x;
    int node0 = blockIdx.x * 64;

    // Stage W rows 0..63 of [W_K | W_Q]
    for (int i = tid; i < 64 * 64; i += 512) {
        int k = i >> 6;
        int j = (i & 63) * 4;
        float4 v;
        if (j < 128) v = *reinterpret_cast<const float4*>(WK + k * 128 + j);
        else         v = *reinterpret_cast<const float4*>(WQ + k * 128 + (j - 128));
        *reinterpret_cast<float4*>(sW + k * 256 + j) = v;
    }
    // Stage agg tile transposed via float4 loads: i -> (node n, k-quad)
    for (int i = tid; i < 64 * 16; i += 512) {
        int n  = i >> 4;           // 0..63
        int k4 = (i & 15) * 4;     // 0..60
        int gn = node0 + n;
        float4 v = (gn < N)
            ? *reinterpret_cast<const float4*>(g_agg + (size_t)gn * F_XD + k4)
            : make_float4(0.f, 0.f, 0.f, 0.f);
        sA[(k4 + 0) * AS2 + n] = v.x;
        sA[(k4 + 1) * AS2 + n] = v.y;
        sA[(k4 + 2) * AS2 + n] = v.z;
        sA[(k4 + 3) * AS2 + n] = v.w;
    }
    if (tid < 64) {
        int gn = node0 + tid;
        int b = 0;
        if (gn < N) {
            if (g_is64) b = (int)((const long long*)batch)[gn];
            else        b = ((const int*)batch)[gn];
        }
        sB[tid] = b;
    }
    __syncthreads();

    int cg = tid & 63;      // 64 col groups x 4 cols (warp-uniform node group)
    int ng = tid >> 6;      // 8 node groups x 8 nodes
    int c0 = cg * 4;
    int n0 = ng * 8;

    ull acc[4][4];
#pragma unroll
    for (int p = 0; p < 4; p++)
#pragma unroll
        for (int c = 0; c < 4; c++) acc[p][c] = 0ull;

#pragma unroll 4
    for (int k = 0; k < 64; k++) {
        // A: two 16B-aligned broadcast loads (AS2 multiple of 4, n0 multiple of 8)
        const float4* ar = reinterpret_cast<const float4*>(sA + k * AS2 + n0);
        float4 av0 = ar[0];
        float4 av1 = ar[1];
        ull a0 = pack2(av0.x, av0.y);
        ull a1 = pack2(av0.z, av0.w);
        ull a2 = pack2(av1.x, av1.y);
        ull a3 = pack2(av1.z, av1.w);

        float4 w = *reinterpret_cast<const float4*>(sW + k * 256 + c0);
        ull w2[4] = { pack2(w.x, w.x), pack2(w.y, w.y),
                      pack2(w.z, w.z), pack2(w.w, w.w) };
#pragma unroll
        for (int c = 0; c < 4; c++) {
            ffma2(acc[0][c], a0, w2[c]);
            ffma2(acc[1][c], a1, w2[c]);
            ffma2(acc[2][c], a2, w2[c]);
            ffma2(acc[3][c], a3, w2[c]);
        }
    }

    float* outK = out;
    float* outQ = out + (size_t)N * 128;

#pragma unroll
    for (int p = 0; p < 4; p++) {
        int nA = n0 + 2 * p, nB = nA + 1;
        int gA = node0 + nA, gB = node0 + nB;
        float4 uA = *reinterpret_cast<const float4*>(g_U + sB[nA] * 256 + c0);
        float4 uB = *reinterpret_cast<const float4*>(g_U + sB[nB] * 256 + c0);

        float2 f0 = *reinterpret_cast<float2*>(&acc[p][0]);
        float2 f1 = *reinterpret_cast<float2*>(&acc[p][1]);
        float2 f2 = *reinterpret_cast<float2*>(&acc[p][2]);
        float2 f3 = *reinterpret_cast<float2*>(&acc[p][3]);

        float4 wa = make_float4(f0.x + uA.x, f1.x + uA.y, f2.x + uA.z, f3.x + uA.w);
        float4 wb = make_float4(f0.y + uB.x, f1.y + uB.y, f2.y + uB.z, f3.y + uB.w);

        if (c0 < 128) {
            if (gA < N) *reinterpret_cast<float4*>(outK + (size_t)gA * 128 + c0) = wa;
            if (gB < N) *reinterpret_cast<float4*>(outK + (size_t)gB * 128 + c0) = wb;
        } else {
            if (gA < N) *reinterpret_cast<float4*>(outQ + (size_t)gA * 128 + (c0 - 128)) = wa;
            if (gB < N) *reinterpret_cast<float4*>(outQ + (size_t)gB * 128 + (c0 - 128)) = wb;
        }
    }
}

// ---------------------------------------------------------------------------
extern "C" void kernel_launch(void* const* d_in, const int* in_sizes, int n_in,
                              void* d_out, int out_size) {
    const float* x     = (const float*)d_in[0];
    const void*  ei    = d_in[1];
    const float* attr  = (const float*)d_in[2];
    const float* u     = (const float*)d_in[3];
    const void*  batch = d_in[4];
    const float* WK    = (const float*)d_in[5];
    const float* bK    = (const float*)d_in[6];
    const float* WQ    = (const float*)d_in[7];
    const float* bQ    = (const float*)d_in[8];
    float*       out   = (float*)d_out;

    int E = in_sizes[2];
    int N = in_sizes[4];
    int nblk = (N + SCAN_B - 1) / SCAN_B;

    zero_probe_kernel<<<(N + 255) / 256, 256>>>(ei, E, N);
    hist_kernel<<<((E >> 2) + 255) / 256, 256>>>(ei, E);
    scan1_kernel<<<nblk, 256>>>(N);
    scan2_kernel<<<1, 512>>>(nblk);
    scan3_kernel<<<nblk, 256>>>(N);
    fill_kernel<<<((E >> 2) + 255) / 256, 256>>>(ei, attr, E);
    agg_kernel<<<(N * 32 + 255) / 256, 256>>>(x, N);

    u_proj_kernel<<<B_GLOB / 4, 256>>>(u, WK, bK, WQ, bQ);

    int smem = (64 * 256 + 64 * AS2) * (int)sizeof(float);
    cudaFuncSetAttribute(proj_kernel, cudaFuncAttributeMaxDynamicSharedMemorySize, smem);
    proj_kernel<<<(N + 63) / 64, 512, smem>>>(batch, WK, WQ, out, N);
}

// round 9
// speedup vs baseline: 1.1970x; 1.0321x over previous
#include <cuda_runtime.h>

#define N_NODES 100000
#define E_MAX   3200000
#define F_XD    64
#define F_UD    128
#define F_OUTD  128
#define B_GLOB  512
#define SCAN_B  1024

typedef unsigned long long ull;

__device__ float g_agg[N_NODES * F_XD];
__device__ float g_U[B_GLOB * 256];
__device__ int   g_is64;
__device__ int   g_deg[N_NODES];
__device__ int   g_rowptr[N_NODES];
__device__ int   g_cursor[N_NODES];
__device__ int   g_bsum[512];
__device__ int   g_boff[512];
__device__ uint2 g_edges[E_MAX];

__device__ __forceinline__ ull pack2(float a, float b) {
    ull r; asm("mov.b64 %0, {%1, %2};" : "=l"(r) : "f"(a), "f"(b)); return r;
}
__device__ __forceinline__ void ffma2(ull& d, ull a, ull b) {
    asm("fma.rn.f32x2 %0, %1, %2, %0;" : "+l"(d) : "l"(a), "l"(b));
}
__device__ __forceinline__ ull add2(ull a, ull b) {
    ull r; asm("add.rn.f32x2 %0, %1, %2;" : "=l"(r) : "l"(a), "l"(b)); return r;
}

// ---------------------------------------------------------------------------
// zero degree counters + index-dtype probe  (R4 verbatim)
// ---------------------------------------------------------------------------
__global__ void zero_probe_kernel(const void* __restrict__ ei, int E, int N) {
    int i = blockIdx.x * blockDim.x + threadIdx.x;
    if (i < N) g_deg[i] = 0;
    if (i == 0) {
        const long long* p = (const long long*)ei;
        long long stride = (2LL * E) / 64;
        int ok = 1;
        for (int j = 0; j < 64; j++) {
            long long v = p[(long long)j * stride];
            if (v < 0 || v >= N) { ok = 0; break; }
        }
        g_is64 = ok;
    }
}

// ---------------------------------------------------------------------------
// in-degree histogram (R4 verbatim)
// ---------------------------------------------------------------------------
__global__ void hist_kernel(const void* __restrict__ ei, int E) {
    const int is64 = g_is64;
    int t = blockIdx.x * blockDim.x + threadIdx.x;
    if (!is64 && (E & 3) == 0) {
        int n4 = E >> 2;
        if (t >= n4) return;
        int4 d4 = reinterpret_cast<const int4*>((const int*)ei + E)[t];
        atomicAdd(&g_deg[d4.x], 1);
        atomicAdd(&g_deg[d4.y], 1);
        atomicAdd(&g_deg[d4.z], 1);
        atomicAdd(&g_deg[d4.w], 1);
    } else {
        for (int e = t; e < E; e += gridDim.x * blockDim.x) {
            int d = is64 ? (int)((const long long*)ei)[E + e]
                         : ((const int*)ei)[E + e];
            atomicAdd(&g_deg[d], 1);
        }
    }
}

// ---------------------------------------------------------------------------
// Exclusive scan; scan2 parallelized (only change vs R4)
// ---------------------------------------------------------------------------
__global__ void scan1_kernel(int N) {
    __shared__ int ss[256];
    int b = blockIdx.x, t = threadIdx.x;
    int base = b * SCAN_B + t * 4;
    int s = 0;
#pragma unroll
    for (int j = 0; j < 4; j++) { int idx = base + j; if (idx < N) s += g_deg[idx]; }
    ss[t] = s;
    __syncthreads();
    for (int off = 128; off > 0; off >>= 1) {
        if (t < off) ss[t] += ss[t + off];
        __syncthreads();
    }
    if (t == 0) g_bsum[b] = ss[0];
}

__global__ void scan2_kernel(int nblk) {
    __shared__ int ss[512];
    int t = threadIdx.x;
    int v = (t < nblk) ? g_bsum[t] : 0;
    ss[t] = v;
    __syncthreads();
    for (int off = 1; off < 512; off <<= 1) {
        int add = (t >= off) ? ss[t - off] : 0;
        __syncthreads();
        ss[t] += add;
        __syncthreads();
    }
    if (t < nblk) g_boff[t] = ss[t] - v;
}

__global__ void scan3_kernel(int N) {
    __shared__ int ss[256];
    int b = blockIdx.x, t = threadIdx.x;
    int base = b * SCAN_B + t * 4;
    int v[4]; int tsum = 0;
#pragma unroll
    for (int j = 0; j < 4; j++) {
        int idx = base + j;
        v[j] = (idx < N) ? g_deg[idx] : 0;
        tsum += v[j];
    }
    ss[t] = tsum;
    __syncthreads();
    for (int off = 1; off < 256; off <<= 1) {
        int add = (t >= off) ? ss[t - off] : 0;
        __syncthreads();
        ss[t] += add;
        __syncthreads();
    }
    int run = g_boff[b] + ss[t] - tsum;
#pragma unroll
    for (int j = 0; j < 4; j++) {
        int idx = base + j;
        if (idx < N) { g_rowptr[idx] = run; g_cursor[idx] = run; }
        run += v[j];
    }
}

// ---------------------------------------------------------------------------
// bucket edges by dest (R4 verbatim — scalar, max thread count)
// ---------------------------------------------------------------------------
__global__ void fill_kernel(const void*  __restrict__ ei,
                            const float* __restrict__ attr, int E) {
    const int is64 = g_is64;
    int e = blockIdx.x * blockDim.x + threadIdx.x;
    if (e >= E) return;
    int s, d;
    if (is64) { s = (int)((const long long*)ei)[e]; d = (int)((const long long*)ei)[E + e]; }
    else      { s = ((const int*)ei)[e];            d = ((const int*)ei)[E + e]; }
    int pos = atomicAdd(&g_cursor[d], 1);
    g_edges[pos] = make_uint2((unsigned)s, __float_as_uint(attr[e]));
}

// ---------------------------------------------------------------------------
// Aggregate (R4 verbatim): one warp per dest, lane owns 2 cols, 4-edge unroll
// ---------------------------------------------------------------------------
__global__ void __launch_bounds__(256)
agg_kernel(const float* __restrict__ x, int N) {
    int t    = blockIdx.x * blockDim.x + threadIdx.x;
    int lane = t & 31;
    int d    = t >> 5;
    if (d >= N) return;

    int start = g_rowptr[d];
    int deg   = g_deg[d];
    const float* xb = x + lane * 2;

    ull a0 = 0, a1 = 0, a2 = 0, a3 = 0;
    int i = 0;
    for (; i + 4 <= deg; i += 4) {
        uint2 e0 = g_edges[start + i + 0];
        uint2 e1 = g_edges[start + i + 1];
        uint2 e2 = g_edges[start + i + 2];
        uint2 e3 = g_edges[start + i + 3];
        ull v0 = *reinterpret_cast<const ull*>(xb + (size_t)e0.x * F_XD);
        ull v1 = *reinterpret_cast<const ull*>(xb + (size_t)e1.x * F_XD);
        ull v2 = *reinterpret_cast<const ull*>(xb + (size_t)e2.x * F_XD);
        ull v3 = *reinterpret_cast<const ull*>(xb + (size_t)e3.x * F_XD);
        float w0 = __uint_as_float(e0.y), w1 = __uint_as_float(e1.y);
        float w2 = __uint_as_float(e2.y), w3 = __uint_as_float(e3.y);
        ffma2(a0, v0, pack2(w0, w0));
        ffma2(a1, v1, pack2(w1, w1));
        ffma2(a2, v2, pack2(w2, w2));
        ffma2(a3, v3, pack2(w3, w3));
    }
    for (; i < deg; i++) {
        uint2 e0 = g_edges[start + i];
        ull v0 = *reinterpret_cast<const ull*>(xb + (size_t)e0.x * F_XD);
        float w0 = __uint_as_float(e0.y);
        ffma2(a0, v0, pack2(w0, w0));
    }
    ull s = add2(add2(a0, a1), add2(a2, a3));
    *reinterpret_cast<ull*>(g_agg + (size_t)d * F_XD + lane * 2) = s;
}

// ---------------------------------------------------------------------------
// u-projection (R4 verbatim)
// ---------------------------------------------------------------------------
__global__ void u_proj_kernel(const float* __restrict__ u,
                              const float* __restrict__ WK, const float* __restrict__ bK,
                              const float* __restrict__ WQ, const float* __restrict__ bQ) {
    __shared__ float su[4][F_UD];
    int b0 = blockIdx.x * 4;
    int j  = threadIdx.x;
    for (int i = j; i < 4 * F_UD; i += 256)
        su[i >> 7][i & 127] = u[(b0 + (i >> 7)) * F_UD + (i & 127)];
    __syncthreads();

    const float* W   = (j < F_OUTD) ? WK : WQ;
    int          col = j & (F_OUTD - 1);
    float bias = (j < F_OUTD) ? bK[col] : bQ[col];
    float a0 = bias, a1 = bias, a2 = bias, a3 = bias;
#pragma unroll 4
    for (int k = 0; k < F_UD; k++) {
        float wv = W[(F_XD + k) * F_OUTD + col];
        a0 = fmaf(su[0][k], wv, a0);
        a1 = fmaf(su[1][k], wv, a1);
        a2 = fmaf(su[2][k], wv, a2);
        a3 = fmaf(su[3][k], wv, a3);
    }
    g_U[(b0 + 0) * 256 + j] = a0;
    g_U[(b0 + 1) * 256 + j] = a1;
    g_U[(b0 + 2) * 256 + j] = a2;
    g_U[(b0 + 3) * 256 + j] = a3;
}

// ---------------------------------------------------------------------------
// Fused projection: R4 tile/inner-loop, but PERSISTENT over node tiles:
// sW staged ONCE per block, then grid-stride loop restaging only sA/sB.
// ---------------------------------------------------------------------------
#define AS2 66
#define PROJ_GRID 296

__global__ void __launch_bounds__(512)
proj_kernel(const void* __restrict__ batch,
            const float* __restrict__ WK,
            const float* __restrict__ WQ,
            float* __restrict__ out, int N) {
    extern __shared__ float sh[];
    float* sW = sh;                 // [64][256]
    float* sA = sh + 64 * 256;      // [64][AS2]
    __shared__ int sB[64];

    int tid = threadIdx.x;

    // Stage W rows 0..63 of [W_K | W_Q] — once per block
    for (int i = tid; i < 64 * 64; i += 512) {
        int k = i >> 6;
        int j = (i & 63) * 4;
        float4 v;
        if (j < 128) v = *reinterpret_cast<const float4*>(WK + k * 128 + j);
        else         v = *reinterpret_cast<const float4*>(WQ + k * 128 + (j - 128));
        *reinterpret_cast<float4*>(sW + k * 256 + j) = v;
    }

    const int is64   = g_is64;
    const int ntiles = (N + 63) / 64;
    float* outK = out;
    float* outQ = out + (size_t)N * 128;

    int cg = tid & 63;      // 64 col groups x 4 cols (node group warp-uniform)
    int ng = tid >> 6;      // 8 node groups x 8 nodes
    int c0 = cg * 4;
    int n0 = ng * 8;

    for (int tile = blockIdx.x; tile < ntiles; tile += PROJ_GRID) {
        int node0 = tile * 64;

        __syncthreads();   // protect sA/sB against previous iteration readers

        for (int i = tid; i < 64 * 64; i += 512) {
            int n = i >> 6;
            int k = i & 63;
            int gn = node0 + n;
            sA[k * AS2 + n] = (gn < N) ? g_agg[(size_t)gn * F_XD + k] : 0.f;
        }
        if (tid < 64) {
            int gn = node0 + tid;
            int b = 0;
            if (gn < N) {
                if (is64) b = (int)((const long long*)batch)[gn];
                else      b = ((const int*)batch)[gn];
            }
            sB[tid] = b;
        }
        __syncthreads();

        ull acc[4][4];
#pragma unroll
        for (int p = 0; p < 4; p++)
#pragma unroll
            for (int c = 0; c < 4; c++) acc[p][c] = 0ull;

#pragma unroll 4
        for (int k = 0; k < 64; k++) {
            float4 w = *reinterpret_cast<const float4*>(sW + k * 256 + c0);
            ull w2[4] = { pack2(w.x, w.x), pack2(w.y, w.y),
                          pack2(w.z, w.z), pack2(w.w, w.w) };
            const float* ar = sA + k * AS2 + n0;
            ull a0 = *reinterpret_cast<const ull*>(ar + 0);
            ull a1 = *reinterpret_cast<const ull*>(ar + 2);
            ull a2 = *reinterpret_cast<const ull*>(ar + 4);
            ull a3 = *reinterpret_cast<const ull*>(ar + 6);
#pragma unroll
            for (int c = 0; c < 4; c++) {
                ffma2(acc[0][c], a0, w2[c]);
                ffma2(acc[1][c], a1, w2[c]);
                ffma2(acc[2][c], a2, w2[c]);
                ffma2(acc[3][c], a3, w2[c]);
            }
        }

#pragma unroll
        for (int p = 0; p < 4; p++) {
            int nA = n0 + 2 * p, nB = nA + 1;
            int gA = node0 + nA, gB = node0 + nB;
            float4 uA = *reinterpret_cast<const float4*>(g_U + sB[nA] * 256 + c0);
            float4 uB = *reinterpret_cast<const float4*>(g_U + sB[nB] * 256 + c0);

            float2 f0 = *reinterpret_cast<float2*>(&acc[p][0]);
            float2 f1 = *reinterpret_cast<float2*>(&acc[p][1]);
            float2 f2 = *reinterpret_cast<float2*>(&acc[p][2]);
            float2 f3 = *reinterpret_cast<float2*>(&acc[p][3]);

            float4 wa = make_float4(f0.x + uA.x, f1.x + uA.y, f2.x + uA.z, f3.x + uA.w);
            float4 wb = make_float4(f0.y + uB.x, f1.y + uB.y, f2.y + uB.z, f3.y + uB.w);

            if (c0 < 128) {
                if (gA < N) *reinterpret_cast<float4*>(outK + (size_t)gA * 128 + c0) = wa;
                if (gB < N) *reinterpret_cast<float4*>(outK + (size_t)gB * 128 + c0) = wb;
            } else {
                if (gA < N) *reinterpret_cast<float4*>(outQ + (size_t)gA * 128 + (c0 - 128)) = wa;
                if (gB < N) *reinterpret_cast<float4*>(outQ + (size_t)gB * 128 + (c0 - 128)) = wb;
            }
        }
    }
}

// ---------------------------------------------------------------------------
extern "C" void kernel_launch(void* const* d_in, const int* in_sizes, int n_in,
                              void* d_out, int out_size) {
    const float* x     = (const float*)d_in[0];
    const void*  ei    = d_in[1];
    const float* attr  = (const float*)d_in[2];
    const float* u     = (const float*)d_in[3];
    const void*  batch = d_in[4];
    const float* WK    = (const float*)d_in[5];
    const float* bK    = (const float*)d_in[6];
    const float* WQ    = (const float*)d_in[7];
    const float* bQ    = (const float*)d_in[8];
    float*       out   = (float*)d_out;

    int E = in_sizes[2];
    int N = in_sizes[4];
    int nblk = (N + SCAN_B - 1) / SCAN_B;

    zero_probe_kernel<<<(N + 255) / 256, 256>>>(ei, E, N);
    hist_kernel<<<((E >> 2) + 255) / 256, 256>>>(ei, E);
    scan1_kernel<<<nblk, 256>>>(N);
    scan2_kernel<<<1, 512>>>(nblk);
    scan3_kernel<<<nblk, 256>>>(N);
    fill_kernel<<<(E + 255) / 256, 256>>>(ei, attr, E);
    agg_kernel<<<(N * 32 + 255) / 256, 256>>>(x, N);

    u_proj_kernel<<<B_GLOB / 4, 256>>>(u, WK, bK, WQ, bQ);

    int smem = (64 * 256 + 64 * AS2) * (int)sizeof(float);
    cudaFuncSetAttribute(proj_kernel, cudaFuncAttributeMaxDynamicSharedMemorySize, smem);
    proj_kernel<<<PROJ_GRID, 512, smem>>>(batch, WK, WQ, out, N);
}

// round 10
// speedup vs baseline: 1.2199x; 1.0191x over previous
#include <cuda_runtime.h>
#include <cuda_fp16.h>

#define N_NODES 100000
#define E_MAX   3200000
#define F_XD    64
#define F_UD    128
#define F_OUTD  128
#define B_GLOB  512
#define SCAN_B  1024

typedef unsigned long long ull;

__device__ float   g_agg[N_NODES * F_XD];
__device__ __half2 g_xh2[N_NODES * 32];        // fp16 copy of x, 12.8 MB
__device__ float   g_U[B_GLOB * 256];
__device__ int     g_is64;
__device__ int     g_deg[N_NODES];
__device__ int     g_rowptr[N_NODES];
__device__ int     g_cursor[N_NODES];
__device__ int     g_bsum[512];
__device__ int     g_boff[512];
__device__ uint2   g_edges[E_MAX];

__device__ __forceinline__ ull pack2(float a, float b) {
    ull r; asm("mov.b64 %0, {%1, %2};" : "=l"(r) : "f"(a), "f"(b)); return r;
}
__device__ __forceinline__ void ffma2(ull& d, ull a, ull b) {
    asm("fma.rn.f32x2 %0, %1, %2, %0;" : "+l"(d) : "l"(a), "l"(b));
}
__device__ __forceinline__ ull add2(ull a, ull b) {
    ull r; asm("add.rn.f32x2 %0, %1, %2;" : "=l"(r) : "l"(a), "l"(b)); return r;
}

// ---------------------------------------------------------------------------
// zero degree counters + index-dtype probe  (R4 verbatim)
// ---------------------------------------------------------------------------
__global__ void zero_probe_kernel(const void* __restrict__ ei, int E, int N) {
    int i = blockIdx.x * blockDim.x + threadIdx.x;
    if (i < N) g_deg[i] = 0;
    if (i == 0) {
        const long long* p = (const long long*)ei;
        long long stride = (2LL * E) / 64;
        int ok = 1;
        for (int j = 0; j < 64; j++) {
            long long v = p[(long long)j * stride];
            if (v < 0 || v >= N) { ok = 0; break; }
        }
        g_is64 = ok;
    }
}

// ---------------------------------------------------------------------------
// convert x (fp32) -> g_xh2 (fp16) : halves the gather traffic in agg
// ---------------------------------------------------------------------------
__global__ void xcvt_kernel(const float* __restrict__ x, int n2) {
    int i = blockIdx.x * blockDim.x + threadIdx.x;
    if (i < n2) {
        float2 v = reinterpret_cast<const float2*>(x)[i];
        g_xh2[i] = __float22half2_rn(v);
    }
}

// ---------------------------------------------------------------------------
// in-degree histogram (R4 verbatim)
// ---------------------------------------------------------------------------
__global__ void hist_kernel(const void* __restrict__ ei, int E) {
    const int is64 = g_is64;
    int t = blockIdx.x * blockDim.x + threadIdx.x;
    if (!is64 && (E & 3) == 0) {
        int n4 = E >> 2;
        if (t >= n4) return;
        int4 d4 = reinterpret_cast<const int4*>((const int*)ei + E)[t];
        atomicAdd(&g_deg[d4.x], 1);
        atomicAdd(&g_deg[d4.y], 1);
        atomicAdd(&g_deg[d4.z], 1);
        atomicAdd(&g_deg[d4.w], 1);
    } else {
        for (int e = t; e < E; e += gridDim.x * blockDim.x) {
            int d = is64 ? (int)((const long long*)ei)[E + e]
                         : ((const int*)ei)[E + e];
            atomicAdd(&g_deg[d], 1);
        }
    }
}

// ---------------------------------------------------------------------------
// Exclusive scan (scan2 parallel; scan1/scan3 R4 verbatim)
// ---------------------------------------------------------------------------
__global__ void scan1_kernel(int N) {
    __shared__ int ss[256];
    int b = blockIdx.x, t = threadIdx.x;
    int base = b * SCAN_B + t * 4;
    int s = 0;
#pragma unroll
    for (int j = 0; j < 4; j++) { int idx = base + j; if (idx < N) s += g_deg[idx]; }
    ss[t] = s;
    __syncthreads();
    for (int off = 128; off > 0; off >>= 1) {
        if (t < off) ss[t] += ss[t + off];
        __syncthreads();
    }
    if (t == 0) g_bsum[b] = ss[0];
}

__global__ void scan2_kernel(int nblk) {
    __shared__ int ss[512];
    int t = threadIdx.x;
    int v = (t < nblk) ? g_bsum[t] : 0;
    ss[t] = v;
    __syncthreads();
    for (int off = 1; off < 512; off <<= 1) {
        int add = (t >= off) ? ss[t - off] : 0;
        __syncthreads();
        ss[t] += add;
        __syncthreads();
    }
    if (t < nblk) g_boff[t] = ss[t] - v;
}

__global__ void scan3_kernel(int N) {
    __shared__ int ss[256];
    int b = blockIdx.x, t = threadIdx.x;
    int base = b * SCAN_B + t * 4;
    int v[4]; int tsum = 0;
#pragma unroll
    for (int j = 0; j < 4; j++) {
        int idx = base + j;
        v[j] = (idx < N) ? g_deg[idx] : 0;
        tsum += v[j];
    }
    ss[t] = tsum;
    __syncthreads();
    for (int off = 1; off < 256; off <<= 1) {
        int add = (t >= off) ? ss[t - off] : 0;
        __syncthreads();
        ss[t] += add;
        __syncthreads();
    }
    int run = g_boff[b] + ss[t] - tsum;
#pragma unroll
    for (int j = 0; j < 4; j++) {
        int idx = base + j;
        if (idx < N) { g_rowptr[idx] = run; g_cursor[idx] = run; }
        run += v[j];
    }
}

// ---------------------------------------------------------------------------
// bucket edges by dest (R4 verbatim — scalar, max thread count)
// ---------------------------------------------------------------------------
__global__ void fill_kernel(const void*  __restrict__ ei,
                            const float* __restrict__ attr, int E) {
    const int is64 = g_is64;
    int e = blockIdx.x * blockDim.x + threadIdx.x;
    if (e >= E) return;
    int s, d;
    if (is64) { s = (int)((const long long*)ei)[e]; d = (int)((const long long*)ei)[E + e]; }
    else      { s = ((const int*)ei)[e];            d = ((const int*)ei)[E + e]; }
    int pos = atomicAdd(&g_cursor[d], 1);
    g_edges[pos] = make_uint2((unsigned)s, __float_as_uint(attr[e]));
}

// ---------------------------------------------------------------------------
// Aggregate: one warp per dest, lane owns 2 cols; fp16 gather (4B per lane
// per edge), fp32 accumulation. 4-edge unroll -> MLP=4.
// ---------------------------------------------------------------------------
__global__ void __launch_bounds__(256)
agg_kernel(int N) {
    int t    = blockIdx.x * blockDim.x + threadIdx.x;
    int lane = t & 31;
    int d    = t >> 5;
    if (d >= N) return;

    int start = g_rowptr[d];
    int deg   = g_deg[d];
    const __half2* xb = g_xh2 + lane;    // row r at xb[r*32]

    ull a0 = 0, a1 = 0, a2 = 0, a3 = 0;
    int i = 0;
    for (; i + 4 <= deg; i += 4) {
        uint2 e0 = g_edges[start + i + 0];
        uint2 e1 = g_edges[start + i + 1];
        uint2 e2 = g_edges[start + i + 2];
        uint2 e3 = g_edges[start + i + 3];
        __half2 h0 = xb[(size_t)e0.x * 32];
        __half2 h1 = xb[(size_t)e1.x * 32];
        __half2 h2 = xb[(size_t)e2.x * 32];
        __half2 h3 = xb[(size_t)e3.x * 32];
        float2 f0 = __half22float2(h0);
        float2 f1 = __half22float2(h1);
        float2 f2 = __half22float2(h2);
        float2 f3 = __half22float2(h3);
        float w0 = __uint_as_float(e0.y), w1 = __uint_as_float(e1.y);
        float w2 = __uint_as_float(e2.y), w3 = __uint_as_float(e3.y);
        ffma2(a0, pack2(f0.x, f0.y), pack2(w0, w0));
        ffma2(a1, pack2(f1.x, f1.y), pack2(w1, w1));
        ffma2(a2, pack2(f2.x, f2.y), pack2(w2, w2));
        ffma2(a3, pack2(f3.x, f3.y), pack2(w3, w3));
    }
    for (; i < deg; i++) {
        uint2 e0 = g_edges[start + i];
        __half2 h0 = xb[(size_t)e0.x * 32];
        float2 f0 = __half22float2(h0);
        float w0 = __uint_as_float(e0.y);
        ffma2(a0, pack2(f0.x, f0.y), pack2(w0, w0));
    }
    ull s = add2(add2(a0, a1), add2(a2, a3));
    *reinterpret_cast<ull*>(g_agg + (size_t)d * F_XD + lane * 2) = s;
}

// ---------------------------------------------------------------------------
// u-projection (R4 verbatim)
// ---------------------------------------------------------------------------
__global__ void u_proj_kernel(const float* __restrict__ u,
                              const float* __restrict__ WK, const float* __restrict__ bK,
                              const float* __restrict__ WQ, const float* __restrict__ bQ) {
    __shared__ float su[4][F_UD];
    int b0 = blockIdx.x * 4;
    int j  = threadIdx.x;
    for (int i = j; i < 4 * F_UD; i += 256)
        su[i >> 7][i & 127] = u[(b0 + (i >> 7)) * F_UD + (i & 127)];
    __syncthreads();

    const float* W   = (j < F_OUTD) ? WK : WQ;
    int          col = j & (F_OUTD - 1);
    float bias = (j < F_OUTD) ? bK[col] : bQ[col];
    float a0 = bias, a1 = bias, a2 = bias, a3 = bias;
#pragma unroll 4
    for (int k = 0; k < F_UD; k++) {
        float wv = W[(F_XD + k) * F_OUTD + col];
        a0 = fmaf(su[0][k], wv, a0);
        a1 = fmaf(su[1][k], wv, a1);
        a2 = fmaf(su[2][k], wv, a2);
        a3 = fmaf(su[3][k], wv, a3);
    }
    g_U[(b0 + 0) * 256 + j] = a0;
    g_U[(b0 + 1) * 256 + j] = a1;
    g_U[(b0 + 2) * 256 + j] = a2;
    g_U[(b0 + 3) * 256 + j] = a3;
}

// ---------------------------------------------------------------------------
// Fused projection (R4 champion verbatim): 64-node tile, 512 threads.
// ---------------------------------------------------------------------------
#define AS2 66

__global__ void __launch_bounds__(512)
proj_kernel(const void* __restrict__ batch,
            const float* __restrict__ WK,
            const float* __restrict__ WQ,
            float* __restrict__ out, int N) {
    extern __shared__ float sh[];
    float* sW = sh;                 // [64][256]
    float* sA = sh + 64 * 256;      // [64][AS2]
    __shared__ int sB[64];

    int tid   = threadIdx.x;
    int node0 = blockIdx.x * 64;

    for (int i = tid; i < 64 * 64; i += 512) {
        int k = i >> 6;
        int j = (i & 63) * 4;
        float4 v;
        if (j < 128) v = *reinterpret_cast<const float4*>(WK + k * 128 + j);
        else         v = *reinterpret_cast<const float4*>(WQ + k * 128 + (j - 128));
        *reinterpret_cast<float4*>(sW + k * 256 + j) = v;
    }
    for (int i = tid; i < 64 * 64; i += 512) {
        int n = i >> 6;
        int k = i & 63;
        int gn = node0 + n;
        sA[k * AS2 + n] = (gn < N) ? g_agg[(size_t)gn * F_XD + k] : 0.f;
    }
    if (tid < 64) {
        int gn = node0 + tid;
        int b = 0;
        if (gn < N) {
            if (g_is64) b = (int)((const long long*)batch)[gn];
            else        b = ((const int*)batch)[gn];
        }
        sB[tid] = b;
    }
    __syncthreads();

    int cg = tid & 63;
    int ng = tid >> 6;
    int c0 = cg * 4;
    int n0 = ng * 8;

    ull acc[4][4];
#pragma unroll
    for (int p = 0; p < 4; p++)
#pragma unroll
        for (int c = 0; c < 4; c++) acc[p][c] = 0ull;

#pragma unroll 4
    for (int k = 0; k < 64; k++) {
        float4 w = *reinterpret_cast<const float4*>(sW + k * 256 + c0);
        ull w2[4] = { pack2(w.x, w.x), pack2(w.y, w.y),
                      pack2(w.z, w.z), pack2(w.w, w.w) };
        const float* ar = sA + k * AS2 + n0;
        ull a0 = *reinterpret_cast<const ull*>(ar + 0);
        ull a1 = *reinterpret_cast<const ull*>(ar + 2);
        ull a2 = *reinterpret_cast<const ull*>(ar + 4);
        ull a3 = *reinterpret_cast<const ull*>(ar + 6);
#pragma unroll
        for (int c = 0; c < 4; c++) {
            ffma2(acc[0][c], a0, w2[c]);
            ffma2(acc[1][c], a1, w2[c]);
            ffma2(acc[2][c], a2, w2[c]);
            ffma2(acc[3][c], a3, w2[c]);
        }
    }

    float* outK = out;
    float* outQ = out + (size_t)N * 128;

#pragma unroll
    for (int p = 0; p < 4; p++) {
        int nA = n0 + 2 * p, nB = nA + 1;
        int gA = node0 + nA, gB = node0 + nB;
        float4 uA = *reinterpret_cast<const float4*>(g_U + sB[nA] * 256 + c0);
        float4 uB = *reinterpret_cast<const float4*>(g_U + sB[nB] * 256 + c0);

        float2 f0 = *reinterpret_cast<float2*>(&acc[p][0]);
        float2 f1 = *reinterpret_cast<float2*>(&acc[p][1]);
        float2 f2 = *reinterpret_cast<float2*>(&acc[p][2]);
        float2 f3 = *reinterpret_cast<float2*>(&acc[p][3]);

        float4 wa = make_float4(f0.x + uA.x, f1.x + uA.y, f2.x + uA.z, f3.x + uA.w);
        float4 wb = make_float4(f0.y + uB.x, f1.y + uB.y, f2.y + uB.z, f3.y + uB.w);

        if (c0 < 128) {
            if (gA < N) *reinterpret_cast<float4*>(outK + (size_t)gA * 128 + c0) = wa;
            if (gB < N) *reinterpret_cast<float4*>(outK + (size_t)gB * 128 + c0) = wb;
        } else {
            if (gA < N) *reinterpret_cast<float4*>(outQ + (size_t)gA * 128 + (c0 - 128)) = wa;
            if (gB < N) *reinterpret_cast<float4*>(outQ + (size_t)gB * 128 + (c0 - 128)) = wb;
        }
    }
}

// ---------------------------------------------------------------------------
extern "C" void kernel_launch(void* const* d_in, const int* in_sizes, int n_in,
                              void* d_out, int out_size) {
    const float* x     = (const float*)d_in[0];
    const void*  ei    = d_in[1];
    const float* attr  = (const float*)d_in[2];
    const float* u     = (const float*)d_in[3];
    const void*  batch = d_in[4];
    const float* WK    = (const float*)d_in[5];
    const float* bK    = (const float*)d_in[6];
    const float* WQ    = (const float*)d_in[7];
    const float* bQ    = (const float*)d_in[8];
    float*       out   = (float*)d_out;

    int E = in_sizes[2];
    int N = in_sizes[4];
    int nblk = (N + SCAN_B - 1) / SCAN_B;

    zero_probe_kernel<<<(N + 255) / 256, 256>>>(ei, E, N);
    xcvt_kernel<<<(N * 32 + 255) / 256, 256>>>(x, N * 32);
    hist_kernel<<<((E >> 2) + 255) / 256, 256>>>(ei, E);
    scan1_kernel<<<nblk, 256>>>(N);
    scan2_kernel<<<1, 512>>>(nblk);
    scan3_kernel<<<nblk, 256>>>(N);
    fill_kernel<<<(E + 255) / 256, 256>>>(ei, attr, E);
    agg_kernel<<<(N * 32 + 255) / 256, 256>>>(N);

    u_proj_kernel<<<B_GLOB / 4, 256>>>(u, WK, bK, WQ, bQ);

    int smem = (64 * 256 + 64 * AS2) * (int)sizeof(float);
    cudaFuncSetAttribute(proj_kernel, cudaFuncAttributeMaxDynamicSharedMemorySize, smem);
    proj_kernel<<<(N + 63) / 64, 512, smem>>>(batch, WK, WQ, out, N);
}

// round 11
// speedup vs baseline: 1.3775x; 1.1293x over previous
#include <cuda_runtime.h>
#include <cuda_fp16.h>

#define N_NODES 100000
#define E_MAX   3200000
#define F_XD    64
#define F_UD    128
#define F_OUTD  128
#define B_GLOB  512
#define SCAN_B  1024

typedef unsigned long long ull;

__device__ float g_agg[N_NODES * F_XD];
__device__ uint4 g_xh[N_NODES * 8];            // fp16 copy of x (row=128B), 12.8 MB
__device__ float g_U[B_GLOB * 256];
__device__ int   g_is64;
__device__ int   g_deg[N_NODES];
__device__ int   g_rowptr[N_NODES];
__device__ int   g_cursor[N_NODES];
__device__ int   g_bsum[512];
__device__ int   g_boff[512];
__device__ uint2 g_edges[E_MAX];

__device__ __forceinline__ ull pack2(float a, float b) {
    ull r; asm("mov.b64 %0, {%1, %2};" : "=l"(r) : "f"(a), "f"(b)); return r;
}
__device__ __forceinline__ void ffma2(ull& d, ull a, ull b) {
    asm("fma.rn.f32x2 %0, %1, %2, %0;" : "+l"(d) : "l"(a), "l"(b));
}
__device__ __forceinline__ ull h2f2(unsigned h) {
    float2 f = __half22float2(*reinterpret_cast<__half2*>(&h));
    return pack2(f.x, f.y);
}

// ---------------------------------------------------------------------------
// zero degree counters + index-dtype probe
// ---------------------------------------------------------------------------
__global__ void zero_probe_kernel(const void* __restrict__ ei, int E, int N) {
    int i = blockIdx.x * blockDim.x + threadIdx.x;
    if (i < N) g_deg[i] = 0;
    if (i == 0) {
        const long long* p = (const long long*)ei;
        long long stride = (2LL * E) / 64;
        int ok = 1;
        for (int j = 0; j < 64; j++) {
            long long v = p[(long long)j * stride];
            if (v < 0 || v >= N) { ok = 0; break; }
        }
        g_is64 = ok;
    }
}

// ---------------------------------------------------------------------------
// convert x (fp32) -> g_xh (fp16 rows of 128B); thread i -> one uint4
// ---------------------------------------------------------------------------
__global__ void xcvt_kernel(const float* __restrict__ x, int n) {   // n = N*8
    int i = blockIdx.x * blockDim.x + threadIdx.x;
    if (i >= n) return;
    float4 v0 = reinterpret_cast<const float4*>(x)[i * 2];
    float4 v1 = reinterpret_cast<const float4*>(x)[i * 2 + 1];
    __half2 h0 = __float22half2_rn(make_float2(v0.x, v0.y));
    __half2 h1 = __float22half2_rn(make_float2(v0.z, v0.w));
    __half2 h2 = __float22half2_rn(make_float2(v1.x, v1.y));
    __half2 h3 = __float22half2_rn(make_float2(v1.z, v1.w));
    uint4 o;
    o.x = *reinterpret_cast<unsigned*>(&h0);
    o.y = *reinterpret_cast<unsigned*>(&h1);
    o.z = *reinterpret_cast<unsigned*>(&h2);
    o.w = *reinterpret_cast<unsigned*>(&h3);
    g_xh[i] = o;
}

// ---------------------------------------------------------------------------
// in-degree histogram
// ---------------------------------------------------------------------------
__global__ void hist_kernel(const void* __restrict__ ei, int E) {
    const int is64 = g_is64;
    int t = blockIdx.x * blockDim.x + threadIdx.x;
    if (!is64 && (E & 3) == 0) {
        int n4 = E >> 2;
        if (t >= n4) return;
        int4 d4 = reinterpret_cast<const int4*>((const int*)ei + E)[t];
        atomicAdd(&g_deg[d4.x], 1);
        atomicAdd(&g_deg[d4.y], 1);
        atomicAdd(&g_deg[d4.z], 1);
        atomicAdd(&g_deg[d4.w], 1);
    } else {
        for (int e = t; e < E; e += gridDim.x * blockDim.x) {
            int d = is64 ? (int)((const long long*)ei)[E + e]
                         : ((const int*)ei)[E + e];
            atomicAdd(&g_deg[d], 1);
        }
    }
}

// ---------------------------------------------------------------------------
// Exclusive scan (3 phases)
// ---------------------------------------------------------------------------
__global__ void scan1_kernel(int N) {
    __shared__ int ss[256];
    int b = blockIdx.x, t = threadIdx.x;
    int base = b * SCAN_B + t * 4;
    int s = 0;
#pragma unroll
    for (int j = 0; j < 4; j++) { int idx = base + j; if (idx < N) s += g_deg[idx]; }
    ss[t] = s;
    __syncthreads();
    for (int off = 128; off > 0; off >>= 1) {
        if (t < off) ss[t] += ss[t + off];
        __syncthreads();
    }
    if (t == 0) g_bsum[b] = ss[0];
}

__global__ void scan2_kernel(int nblk) {
    __shared__ int ss[512];
    int t = threadIdx.x;
    int v = (t < nblk) ? g_bsum[t] : 0;
    ss[t] = v;
    __syncthreads();
    for (int off = 1; off < 512; off <<= 1) {
        int add = (t >= off) ? ss[t - off] : 0;
        __syncthreads();
        ss[t] += add;
        __syncthreads();
    }
    if (t < nblk) g_boff[t] = ss[t] - v;
}

__global__ void scan3_kernel(int N) {
    __shared__ int ss[256];
    int b = blockIdx.x, t = threadIdx.x;
    int base = b * SCAN_B + t * 4;
    int v[4]; int tsum = 0;
#pragma unroll
    for (int j = 0; j < 4; j++) {
        int idx = base + j;
        v[j] = (idx < N) ? g_deg[idx] : 0;
        tsum += v[j];
    }
    ss[t] = tsum;
    __syncthreads();
    for (int off = 1; off < 256; off <<= 1) {
        int add = (t >= off) ? ss[t - off] : 0;
        __syncthreads();
        ss[t] += add;
        __syncthreads();
    }
    int run = g_boff[b] + ss[t] - tsum;
#pragma unroll
    for (int j = 0; j < 4; j++) {
        int idx = base + j;
        if (idx < N) { g_rowptr[idx] = run; g_cursor[idx] = run; }
        run += v[j];
    }
}

// ---------------------------------------------------------------------------
// bucket edges by dest (scalar — max thread count wins here)
// ---------------------------------------------------------------------------
__global__ void fill_kernel(const void*  __restrict__ ei,
                            const float* __restrict__ attr, int E) {
    const int is64 = g_is64;
    int e = blockIdx.x * blockDim.x + threadIdx.x;
    if (e >= E) return;
    int s, d;
    if (is64) { s = (int)((const long long*)ei)[e]; d = (int)((const long long*)ei)[E + e]; }
    else      { s = ((const int*)ei)[e];            d = ((const int*)ei)[E + e]; }
    int pos = atomicAdd(&g_cursor[d], 1);
    g_edges[pos] = make_uint2((unsigned)s, __float_as_uint(attr[e]));
}

// ---------------------------------------------------------------------------
// Aggregate v3: 4 dests per warp, 8 lanes per dest, lane covers 8 fp16 cols
// via ONE LDG.128 per edge-quad.  0.5 LDG per edge (was 2).
// ---------------------------------------------------------------------------
__global__ void __launch_bounds__(256)
agg_kernel(int N) {
    int t    = blockIdx.x * blockDim.x + threadIdx.x;
    int lane = t & 31;
    int grp  = lane >> 3;            // dest group 0..3 within warp
    int l    = lane & 7;             // sublane: cols l*8 .. l*8+7
    int w    = t >> 5;               // global warp id
    int d    = w * 4 + grp;

    int start = 0, deg = 0;
    if (d < N) { start = g_rowptr[d]; deg = g_deg[d]; }

    ull a0 = 0, a1 = 0, a2 = 0, a3 = 0;   // 8 fp32 cols
    int i = 0;
    for (; i + 2 <= deg; i += 2) {
        uint2 e0 = g_edges[start + i];
        uint2 e1 = g_edges[start + i + 1];
        uint4 h0 = *(reinterpret_cast<const uint4*>(g_xh + (size_t)e0.x * 8) + l);
        uint4 h1 = *(reinterpret_cast<const uint4*>(g_xh + (size_t)e1.x * 8) + l);
        float w0 = __uint_as_float(e0.y), w1 = __uint_as_float(e1.y);
        ull w0p = pack2(w0, w0), w1p = pack2(w1, w1);
        ffma2(a0, h2f2(h0.x), w0p);
        ffma2(a1, h2f2(h0.y), w0p);
        ffma2(a2, h2f2(h0.z), w0p);
        ffma2(a3, h2f2(h0.w), w0p);
        ffma2(a0, h2f2(h1.x), w1p);
        ffma2(a1, h2f2(h1.y), w1p);
        ffma2(a2, h2f2(h1.z), w1p);
        ffma2(a3, h2f2(h1.w), w1p);
    }
    if (i < deg) {
        uint2 e0 = g_edges[start + i];
        uint4 h0 = *(reinterpret_cast<const uint4*>(g_xh + (size_t)e0.x * 8) + l);
        float w0 = __uint_as_float(e0.y);
        ull w0p = pack2(w0, w0);
        ffma2(a0, h2f2(h0.x), w0p);
        ffma2(a1, h2f2(h0.y), w0p);
        ffma2(a2, h2f2(h0.z), w0p);
        ffma2(a3, h2f2(h0.w), w0p);
    }

    if (d < N) {
        float2 f0 = *reinterpret_cast<float2*>(&a0);
        float2 f1 = *reinterpret_cast<float2*>(&a1);
        float2 f2 = *reinterpret_cast<float2*>(&a2);
        float2 f3 = *reinterpret_cast<float2*>(&a3);
        float* o = g_agg + (size_t)d * F_XD + l * 8;
        *reinterpret_cast<float4*>(o)     = make_float4(f0.x, f0.y, f1.x, f1.y);
        *reinterpret_cast<float4*>(o + 4) = make_float4(f2.x, f2.y, f3.x, f3.y);
    }
}

// ---------------------------------------------------------------------------
// u-projection: 4 batch rows per block
// ---------------------------------------------------------------------------
__global__ void u_proj_kernel(const float* __restrict__ u,
                              const float* __restrict__ WK, const float* __restrict__ bK,
                              const float* __restrict__ WQ, const float* __restrict__ bQ) {
    __shared__ float su[4][F_UD];
    int b0 = blockIdx.x * 4;
    int j  = threadIdx.x;
    for (int i = j; i < 4 * F_UD; i += 256)
        su[i >> 7][i & 127] = u[(b0 + (i >> 7)) * F_UD + (i & 127)];
    __syncthreads();

    const float* W   = (j < F_OUTD) ? WK : WQ;
    int          col = j & (F_OUTD - 1);
    float bias = (j < F_OUTD) ? bK[col] : bQ[col];
    float a0 = bias, a1 = bias, a2 = bias, a3 = bias;
#pragma unroll 4
    for (int k = 0; k < F_UD; k++) {
        float wv = W[(F_XD + k) * F_OUTD + col];
        a0 = fmaf(su[0][k], wv, a0);
        a1 = fmaf(su[1][k], wv, a1);
        a2 = fmaf(su[2][k], wv, a2);
        a3 = fmaf(su[3][k], wv, a3);
    }
    g_U[(b0 + 0) * 256 + j] = a0;
    g_U[(b0 + 1) * 256 + j] = a1;
    g_U[(b0 + 2) * 256 + j] = a2;
    g_U[(b0 + 3) * 256 + j] = a3;
}

// ---------------------------------------------------------------------------
// Fused projection (R4 champion verbatim): 64-node tile, 512 threads.
// ---------------------------------------------------------------------------
#define AS2 66

__global__ void __launch_bounds__(512)
proj_kernel(const void* __restrict__ batch,
            const float* __restrict__ WK,
            const float* __restrict__ WQ,
            float* __restrict__ out, int N) {
    extern __shared__ float sh[];
    float* sW = sh;                 // [64][256]
    float* sA = sh + 64 * 256;      // [64][AS2]
    __shared__ int sB[64];

    int tid   = threadIdx.x;
    int node0 = blockIdx.x * 64;

    for (int i = tid; i < 64 * 64; i += 512) {
        int k = i >> 6;
        int j = (i & 63) * 4;
        float4 v;
        if (j < 128) v = *reinterpret_cast<const float4*>(WK + k * 128 + j);
        else         v = *reinterpret_cast<const float4*>(WQ + k * 128 + (j - 128));
        *reinterpret_cast<float4*>(sW + k * 256 + j) = v;
    }
    for (int i = tid; i < 64 * 64; i += 512) {
        int n = i >> 6;
        int k = i & 63;
        int gn = node0 + n;
        sA[k * AS2 + n] = (gn < N) ? g_agg[(size_t)gn * F_XD + k] : 0.f;
    }
    if (tid < 64) {
        int gn = node0 + tid;
        int b = 0;
        if (gn < N) {
            if (g_is64) b = (int)((const long long*)batch)[gn];
            else        b = ((const int*)batch)[gn];
        }
        sB[tid] = b;
    }
    __syncthreads();

    int cg = tid & 63;
    int ng = tid >> 6;
    int c0 = cg * 4;
    int n0 = ng * 8;

    ull acc[4][4];
#pragma unroll
    for (int p = 0; p < 4; p++)
#pragma unroll
        for (int c = 0; c < 4; c++) acc[p][c] = 0ull;

#pragma unroll 4
    for (int k = 0; k < 64; k++) {
        float4 w = *reinterpret_cast<const float4*>(sW + k * 256 + c0);
        ull w2[4] = { pack2(w.x, w.x), pack2(w.y, w.y),
                      pack2(w.z, w.z), pack2(w.w, w.w) };
        const float* ar = sA + k * AS2 + n0;
        ull a0 = *reinterpret_cast<const ull*>(ar + 0);
        ull a1 = *reinterpret_cast<const ull*>(ar + 2);
        ull a2 = *reinterpret_cast<const ull*>(ar + 4);
        ull a3 = *reinterpret_cast<const ull*>(ar + 6);
#pragma unroll
        for (int c = 0; c < 4; c++) {
            ffma2(acc[0][c], a0, w2[c]);
            ffma2(acc[1][c], a1, w2[c]);
            ffma2(acc[2][c], a2, w2[c]);
            ffma2(acc[3][c], a3, w2[c]);
        }
    }

    float* outK = out;
    float* outQ = out + (size_t)N * 128;

#pragma unroll
    for (int p = 0; p < 4; p++) {
        int nA = n0 + 2 * p, nB = nA + 1;
        int gA = node0 + nA, gB = node0 + nB;
        float4 uA = *reinterpret_cast<const float4*>(g_U + sB[nA] * 256 + c0);
        float4 uB = *reinterpret_cast<const float4*>(g_U + sB[nB] * 256 + c0);

        float2 f0 = *reinterpret_cast<float2*>(&acc[p][0]);
        float2 f1 = *reinterpret_cast<float2*>(&acc[p][1]);
        float2 f2 = *reinterpret_cast<float2*>(&acc[p][2]);
        float2 f3 = *reinterpret_cast<float2*>(&acc[p][3]);

        float4 wa = make_float4(f0.x + uA.x, f1.x + uA.y, f2.x + uA.z, f3.x + uA.w);
        float4 wb = make_float4(f0.y + uB.x, f1.y + uB.y, f2.y + uB.z, f3.y + uB.w);

        if (c0 < 128) {
            if (gA < N) *reinterpret_cast<float4*>(outK + (size_t)gA * 128 + c0) = wa;
            if (gB < N) *reinterpret_cast<float4*>(outK + (size_t)gB * 128 + c0) = wb;
        } else {
            if (gA < N) *reinterpret_cast<float4*>(outQ + (size_t)gA * 128 + (c0 - 128)) = wa;
            if (gB < N) *reinterpret_cast<float4*>(outQ + (size_t)gB * 128 + (c0 - 128)) = wb;
        }
    }
}

// ---------------------------------------------------------------------------
extern "C" void kernel_launch(void* const* d_in, const int* in_sizes, int n_in,
                              void* d_out, int out_size) {
    const float* x     = (const float*)d_in[0];
    const void*  ei    = d_in[1];
    const float* attr  = (const float*)d_in[2];
    const float* u     = (const float*)d_in[3];
    const void*  batch = d_in[4];
    const float* WK    = (const float*)d_in[5];
    const float* bK    = (const float*)d_in[6];
    const float* WQ    = (const float*)d_in[7];
    const float* bQ    = (const float*)d_in[8];
    float*       out   = (float*)d_out;

    int E = in_sizes[2];
    int N = in_sizes[4];
    int nblk = (N + SCAN_B - 1) / SCAN_B;

    zero_probe_kernel<<<(N + 255) / 256, 256>>>(ei, E, N);
    xcvt_kernel<<<(N * 8 + 255) / 256, 256>>>(x, N * 8);
    hist_kernel<<<((E >> 2) + 255) / 256, 256>>>(ei, E);
    scan1_kernel<<<nblk, 256>>>(N);
    scan2_kernel<<<1, 512>>>(nblk);
    scan3_kernel<<<nblk, 256>>>(N);
    fill_kernel<<<(E + 255) / 256, 256>>>(ei, attr, E);

    int nwarp = (N + 3) / 4;
    agg_kernel<<<(nwarp * 32 + 255) / 256, 256>>>(N);

    u_proj_kernel<<<B_GLOB / 4, 256>>>(u, WK, bK, WQ, bQ);

    int smem = (64 * 256 + 64 * AS2) * (int)sizeof(float);
    cudaFuncSetAttribute(proj_kernel, cudaFuncAttributeMaxDynamicSharedMemorySize, smem);
    proj_kernel<<<(N + 63) / 64, 512, smem>>>(batch, WK, WQ, out, N);
}

// round 12
// speedup vs baseline: 1.3907x; 1.0095x over previous
#include <cuda_runtime.h>
#include <cuda_fp16.h>

#define N_NODES 100000
#define E_MAX   3200000
#define F_XD    64
#define F_UD    128
#define F_OUTD  128
#define B_GLOB  512
#define SCAN_B  1024

typedef unsigned long long ull;

__device__ float g_agg[N_NODES * F_XD];
__device__ uint4 g_xh[N_NODES * 8];            // fp16 copy of x (row=128B), 12.8 MB
__device__ float g_U[B_GLOB * 256];
__device__ int   g_is64;
__device__ int   g_deg[N_NODES];
__device__ int   g_rowptr[N_NODES];
__device__ int   g_cursor[N_NODES];
__device__ int   g_bsum[512];
__device__ int   g_boff[512];
__device__ uint2 g_edges[E_MAX];

__device__ __forceinline__ ull pack2(float a, float b) {
    ull r; asm("mov.b64 %0, {%1, %2};" : "=l"(r) : "f"(a), "f"(b)); return r;
}
__device__ __forceinline__ void ffma2(ull& d, ull a, ull b) {
    asm("fma.rn.f32x2 %0, %1, %2, %0;" : "+l"(d) : "l"(a), "l"(b));
}
__device__ __forceinline__ ull h2f2(unsigned h) {
    float2 f = __half22float2(*reinterpret_cast<__half2*>(&h));
    return pack2(f.x, f.y);
}

// ---------------------------------------------------------------------------
// zero degree counters + index-dtype probe
// ---------------------------------------------------------------------------
__global__ void zero_probe_kernel(const void* __restrict__ ei, int E, int N) {
    int i = blockIdx.x * blockDim.x + threadIdx.x;
    if (i < N) g_deg[i] = 0;
    if (i == 0) {
        const long long* p = (const long long*)ei;
        long long stride = (2LL * E) / 64;
        int ok = 1;
        for (int j = 0; j < 64; j++) {
            long long v = p[(long long)j * stride];
            if (v < 0 || v >= N) { ok = 0; break; }
        }
        g_is64 = ok;
    }
}

// ---------------------------------------------------------------------------
// convert x (fp32) -> g_xh (fp16 rows of 128B); thread i -> one uint4
// ---------------------------------------------------------------------------
__global__ void xcvt_kernel(const float* __restrict__ x, int n) {   // n = N*8
    int i = blockIdx.x * blockDim.x + threadIdx.x;
    if (i >= n) return;
    float4 v0 = reinterpret_cast<const float4*>(x)[i * 2];
    float4 v1 = reinterpret_cast<const float4*>(x)[i * 2 + 1];
    __half2 h0 = __float22half2_rn(make_float2(v0.x, v0.y));
    __half2 h1 = __float22half2_rn(make_float2(v0.z, v0.w));
    __half2 h2 = __float22half2_rn(make_float2(v1.x, v1.y));
    __half2 h3 = __float22half2_rn(make_float2(v1.z, v1.w));
    uint4 o;
    o.x = *reinterpret_cast<unsigned*>(&h0);
    o.y = *reinterpret_cast<unsigned*>(&h1);
    o.z = *reinterpret_cast<unsigned*>(&h2);
    o.w = *reinterpret_cast<unsigned*>(&h3);
    g_xh[i] = o;
}

// ---------------------------------------------------------------------------
// in-degree histogram
// ---------------------------------------------------------------------------
__global__ void hist_kernel(const void* __restrict__ ei, int E) {
    const int is64 = g_is64;
    int t = blockIdx.x * blockDim.x + threadIdx.x;
    if (!is64 && (E & 3) == 0) {
        int n4 = E >> 2;
        if (t >= n4) return;
        int4 d4 = reinterpret_cast<const int4*>((const int*)ei + E)[t];
        atomicAdd(&g_deg[d4.x], 1);
        atomicAdd(&g_deg[d4.y], 1);
        atomicAdd(&g_deg[d4.z], 1);
        atomicAdd(&g_deg[d4.w], 1);
    } else {
        for (int e = t; e < E; e += gridDim.x * blockDim.x) {
            int d = is64 ? (int)((const long long*)ei)[E + e]
                         : ((const int*)ei)[E + e];
            atomicAdd(&g_deg[d], 1);
        }
    }
}

// ---------------------------------------------------------------------------
// Exclusive scan (3 phases)
// ---------------------------------------------------------------------------
__global__ void scan1_kernel(int N) {
    __shared__ int ss[256];
    int b = blockIdx.x, t = threadIdx.x;
    int base = b * SCAN_B + t * 4;
    int s = 0;
#pragma unroll
    for (int j = 0; j < 4; j++) { int idx = base + j; if (idx < N) s += g_deg[idx]; }
    ss[t] = s;
    __syncthreads();
    for (int off = 128; off > 0; off >>= 1) {
        if (t < off) ss[t] += ss[t + off];
        __syncthreads();
    }
    if (t == 0) g_bsum[b] = ss[0];
}

__global__ void scan2_kernel(int nblk) {
    __shared__ int ss[512];
    int t = threadIdx.x;
    int v = (t < nblk) ? g_bsum[t] : 0;
    ss[t] = v;
    __syncthreads();
    for (int off = 1; off < 512; off <<= 1) {
        int add = (t >= off) ? ss[t - off] : 0;
        __syncthreads();
        ss[t] += add;
        __syncthreads();
    }
    if (t < nblk) g_boff[t] = ss[t] - v;
}

__global__ void scan3_kernel(int N) {
    __shared__ int ss[256];
    int b = blockIdx.x, t = threadIdx.x;
    int base = b * SCAN_B + t * 4;
    int v[4]; int tsum = 0;
#pragma unroll
    for (int j = 0; j < 4; j++) {
        int idx = base + j;
        v[j] = (idx < N) ? g_deg[idx] : 0;
        tsum += v[j];
    }
    ss[t] = tsum;
    __syncthreads();
    for (int off = 1; off < 256; off <<= 1) {
        int add = (t >= off) ? ss[t - off] : 0;
        __syncthreads();
        ss[t] += add;
        __syncthreads();
    }
    int run = g_boff[b] + ss[t] - tsum;
#pragma unroll
    for (int j = 0; j < 4; j++) {
        int idx = base + j;
        if (idx < N) { g_rowptr[idx] = run; g_cursor[idx] = run; }
        run += v[j];
    }
}

// ---------------------------------------------------------------------------
// bucket edges by dest (scalar — max thread count wins here)
// ---------------------------------------------------------------------------
__global__ void fill_kernel(const void*  __restrict__ ei,
                            const float* __restrict__ attr, int E) {
    const int is64 = g_is64;
    int e = blockIdx.x * blockDim.x + threadIdx.x;
    if (e >= E) return;
    int s, d;
    if (is64) { s = (int)((const long long*)ei)[e]; d = (int)((const long long*)ei)[E + e]; }
    else      { s = ((const int*)ei)[e];            d = ((const int*)ei)[E + e]; }
    int pos = atomicAdd(&g_cursor[d], 1);
    g_edges[pos] = make_uint2((unsigned)s, __float_as_uint(attr[e]));
}

// ---------------------------------------------------------------------------
// Aggregate v3: 4 dests per warp, 8 lanes per dest, lane covers 8 fp16 cols
// via ONE LDG.128 per edge-quad.  0.5 LDG per edge (was 2).
// ---------------------------------------------------------------------------
__global__ void __launch_bounds__(256)
agg_kernel(int N) {
    int t    = blockIdx.x * blockDim.x + threadIdx.x;
    int lane = t & 31;
    int grp  = lane >> 3;            // dest group 0..3 within warp
    int l    = lane & 7;             // sublane: cols l*8 .. l*8+7
    int w    = t >> 5;               // global warp id
    int d    = w * 4 + grp;

    int start = 0, deg = 0;
    if (d < N) { start = g_rowptr[d]; deg = g_deg[d]; }

    ull a0 = 0, a1 = 0, a2 = 0, a3 = 0;   // 8 fp32 cols
    int i = 0;
    for (; i + 2 <= deg; i += 2) {
        uint2 e0 = g_edges[start + i];
        uint2 e1 = g_edges[start + i + 1];
        uint4 h0 = *(reinterpret_cast<const uint4*>(g_xh + (size_t)e0.x * 8) + l);
        uint4 h1 = *(reinterpret_cast<const uint4*>(g_xh + (size_t)e1.x * 8) + l);
        float w0 = __uint_as_float(e0.y), w1 = __uint_as_float(e1.y);
        ull w0p = pack2(w0, w0), w1p = pack2(w1, w1);
        ffma2(a0, h2f2(h0.x), w0p);
        ffma2(a1, h2f2(h0.y), w0p);
        ffma2(a2, h2f2(h0.z), w0p);
        ffma2(a3, h2f2(h0.w), w0p);
        ffma2(a0, h2f2(h1.x), w1p);
        ffma2(a1, h2f2(h1.y), w1p);
        ffma2(a2, h2f2(h1.z), w1p);
        ffma2(a3, h2f2(h1.w), w1p);
    }
    if (i < deg) {
        uint2 e0 = g_edges[start + i];
        uint4 h0 = *(reinterpret_cast<const uint4*>(g_xh + (size_t)e0.x * 8) + l);
        float w0 = __uint_as_float(e0.y);
        ull w0p = pack2(w0, w0);
        ffma2(a0, h2f2(h0.x), w0p);
        ffma2(a1, h2f2(h0.y), w0p);
        ffma2(a2, h2f2(h0.z), w0p);
        ffma2(a3, h2f2(h0.w), w0p);
    }

    if (d < N) {
        float2 f0 = *reinterpret_cast<float2*>(&a0);
        float2 f1 = *reinterpret_cast<float2*>(&a1);
        float2 f2 = *reinterpret_cast<float2*>(&a2);
        float2 f3 = *reinterpret_cast<float2*>(&a3);
        float* o = g_agg + (size_t)d * F_XD + l * 8;
        *reinterpret_cast<float4*>(o)     = make_float4(f0.x, f0.y, f1.x, f1.y);
        *reinterpret_cast<float4*>(o + 4) = make_float4(f2.x, f2.y, f3.x, f3.y);
    }
}

// ---------------------------------------------------------------------------
// u-projection: 4 batch rows per block
// ---------------------------------------------------------------------------
__global__ void u_proj_kernel(const float* __restrict__ u,
                              const float* __restrict__ WK, const float* __restrict__ bK,
                              const float* __restrict__ WQ, const float* __restrict__ bQ) {
    __shared__ float su[4][F_UD];
    int b0 = blockIdx.x * 4;
    int j  = threadIdx.x;
    for (int i = j; i < 4 * F_UD; i += 256)
        su[i >> 7][i & 127] = u[(b0 + (i >> 7)) * F_UD + (i & 127)];
    __syncthreads();

    const float* W   = (j < F_OUTD) ? WK : WQ;
    int          col = j & (F_OUTD - 1);
    float bias = (j < F_OUTD) ? bK[col] : bQ[col];
    float a0 = bias, a1 = bias, a2 = bias, a3 = bias;
#pragma unroll 4
    for (int k = 0; k < F_UD; k++) {
        float wv = W[(F_XD + k) * F_OUTD + col];
        a0 = fmaf(su[0][k], wv, a0);
        a1 = fmaf(su[1][k], wv, a1);
        a2 = fmaf(su[2][k], wv, a2);
        a3 = fmaf(su[3][k], wv, a3);
    }
    g_U[(b0 + 0) * 256 + j] = a0;
    g_U[(b0 + 1) * 256 + j] = a1;
    g_U[(b0 + 2) * 256 + j] = a2;
    g_U[(b0 + 3) * 256 + j] = a3;
}

// ---------------------------------------------------------------------------
// Fused projection (R4 champion verbatim): 64-node tile, 512 threads.
// ---------------------------------------------------------------------------
#define AS2 66

__global__ void __launch_bounds__(512)
proj_kernel(const void* __restrict__ batch,
            const float* __restrict__ WK,
            const float* __restrict__ WQ,
            float* __restrict__ out, int N) {
    extern __shared__ float sh[];
    float* sW = sh;                 // [64][256]
    float* sA = sh + 64 * 256;      // [64][AS2]
    __shared__ int sB[64];

    int tid   = threadIdx.x;
    int node0 = blockIdx.x * 64;

    for (int i = tid; i < 64 * 64; i += 512) {
        int k = i >> 6;
        int j = (i & 63) * 4;
        float4 v;
        if (j < 128) v = *reinterpret_cast<const float4*>(WK + k * 128 + j);
        else         v = *reinterpret_cast<const float4*>(WQ + k * 128 + (j - 128));
        *reinterpret_cast<float4*>(sW + k * 256 + j) = v;
    }
    for (int i = tid; i < 64 * 64; i += 512) {
        int n = i >> 6;
        int k = i & 63;
        int gn = node0 + n;
        sA[k * AS2 + n] = (gn < N) ? g_agg[(size_t)gn * F_XD + k] : 0.f;
    }
    if (tid < 64) {
        int gn = node0 + tid;
        int b = 0;
        if (gn < N) {
            if (g_is64) b = (int)((const long long*)batch)[gn];
            else        b = ((const int*)batch)[gn];
        }
        sB[tid] = b;
    }
    __syncthreads();

    int cg = tid & 63;
    int ng = tid >> 6;
    int c0 = cg * 4;
    int n0 = ng * 8;

    ull acc[4][4];
#pragma unroll
    for (int p = 0; p < 4; p++)
#pragma unroll
        for (int c = 0; c < 4; c++) acc[p][c] = 0ull;

#pragma unroll 4
    for (int k = 0; k < 64; k++) {
        float4 w = *reinterpret_cast<const float4*>(sW + k * 256 + c0);
        ull w2[4] = { pack2(w.x, w.x), pack2(w.y, w.y),
                      pack2(w.z, w.z), pack2(w.w, w.w) };
        const float* ar = sA + k * AS2 + n0;
        ull a0 = *reinterpret_cast<const ull*>(ar + 0);
        ull a1 = *reinterpret_cast<const ull*>(ar + 2);
        ull a2 = *reinterpret_cast<const ull*>(ar + 4);
        ull a3 = *reinterpret_cast<const ull*>(ar + 6);
#pragma unroll
        for (int c = 0; c < 4; c++) {
            ffma2(acc[0][c], a0, w2[c]);
            ffma2(acc[1][c], a1, w2[c]);
            ffma2(acc[2][c], a2, w2[c]);
            ffma2(acc[3][c], a3, w2[c]);
        }
    }

    float* outK = out;
    float* outQ = out + (size_t)N * 128;

#pragma unroll
    for (int p = 0; p < 4; p++) {
        int nA = n0 + 2 * p, nB = nA + 1;
        int gA = node0 + nA, gB = node0 + nB;
        float4 uA = *reinterpret_cast<const float4*>(g_U + sB[nA] * 256 + c0);
        float4 uB = *reinterpret_cast<const float4*>(g_U + sB[nB] * 256 + c0);

        float2 f0 = *reinterpret_cast<float2*>(&acc[p][0]);
        float2 f1 = *reinterpret_cast<float2*>(&acc[p][1]);
        float2 f2 = *reinterpret_cast<float2*>(&acc[p][2]);
        float2 f3 = *reinterpret_cast<float2*>(&acc[p][3]);

        float4 wa = make_float4(f0.x + uA.x, f1.x + uA.y, f2.x + uA.z, f3.x + uA.w);
        float4 wb = make_float4(f0.y + uB.x, f1.y + uB.y, f2.y + uB.z, f3.y + uB.w);

        if (c0 < 128) {
            if (gA < N) *reinterpret_cast<float4*>(outK + (size_t)gA * 128 + c0) = wa;
            if (gB < N) *reinterpret_cast<float4*>(outK + (size_t)gB * 128 + c0) = wb;
        } else {
            if (gA < N) *reinterpret_cast<float4*>(outQ + (size_t)gA * 128 + (c0 - 128)) = wa;
            if (gB < N) *reinterpret_cast<float4*>(outQ + (size_t)gB * 128 + (c0 - 128)) = wb;
        }
    }
}

// ---------------------------------------------------------------------------
extern "C" void kernel_launch(void* const* d_in, const int* in_sizes, int n_in,
                              void* d_out, int out_size) {
    const float* x     = (const float*)d_in[0];
    const void*  ei    = d_in[1];
    const float* attr  = (const float*)d_in[2];
    const float* u     = (const float*)d_in[3];
    const void*  batch = d_in[4];
    const float* WK    = (const float*)d_in[5];
    const float* bK    = (const float*)d_in[6];
    const float* WQ    = (const float*)d_in[7];
    const float* bQ    = (const float*)d_in[8];
    float*       out   = (float*)d_out;

    int E = in_sizes[2];
    int N = in_sizes[4];
    int nblk = (N + SCAN_B - 1) / SCAN_B;

    zero_probe_kernel<<<(N + 255) / 256, 256>>>(ei, E, N);
    xcvt_kernel<<<(N * 8 + 255) / 256, 256>>>(x, N * 8);
    hist_kernel<<<((E >> 2) + 255) / 256, 256>>>(ei, E);
    scan1_kernel<<<nblk, 256>>>(N);
    scan2_kernel<<<1, 512>>>(nblk);
    scan3_kernel<<<nblk, 256>>>(N);
    fill_kernel<<<(E + 255) / 256, 256>>>(ei, attr, E);

    int nwarp = (N + 3) / 4;
    agg_kernel<<<(nwarp * 32 + 255) / 256, 256>>>(N);

    u_proj_kernel<<<B_GLOB / 4, 256>>>(u, WK, bK, WQ, bQ);

    int smem = (64 * 256 + 64 * AS2) * (int)sizeof(float);
    cudaFuncSetAttribute(proj_kernel, cudaFuncAttributeMaxDynamicSharedMemorySize, smem);
    proj_kernel<<<(N + 63) / 64, 512, smem>>>(batch, WK, WQ, out, N);
}